// round 1
// baseline (speedup 1.0000x reference)
#include <cuda_runtime.h>
#include <cuda_bf16.h>
#include <math.h>

// Problem constants
#define BATCH 2
#define SEQ   2048
#define DIM   2048
#define NH    32
#define NKV   8
#define HD    64
#define KVD   (NKV*HD)   // 512
#define MTOT  (BATCH*SEQ) // 4096

// Scratch (device globals: allocation-free)
__device__ float g_Q [MTOT * DIM];   // 4096 x 2048
__device__ float g_K [MTOT * KVD];   // 4096 x 512
__device__ float g_V [MTOT * KVD];   // 4096 x 512
__device__ float g_AO[MTOT * DIM];   // 4096 x 2048

// ---------------------------------------------------------------------------
// GEMM: C[M,N] = A[M,K] * B[N,K]^T   (both row-major, K contiguous -> "NT")
// 128x128 tile, TK=16, 256 threads, 8x8 per-thread micro-tile.
// ---------------------------------------------------------------------------
#define GT 128
#define TK 16

__global__ __launch_bounds__(256, 2)
void gemm_nt(const float* __restrict__ A, const float* __restrict__ B,
             float* __restrict__ C, int M, int N, int K)
{
    __shared__ float As[TK][GT];
    __shared__ float Bs[TK][GT];

    const int tid = threadIdx.x;
    const int bm  = blockIdx.y * GT;
    const int bn  = blockIdx.x * GT;
    const int trow = (tid >> 4) << 3;   // (tid/16)*8
    const int tcol = (tid & 15) << 3;   // (tid%16)*8

    float acc[8][8];
#pragma unroll
    for (int i = 0; i < 8; i++)
#pragma unroll
        for (int j = 0; j < 8; j++) acc[i][j] = 0.f;

    for (int k0 = 0; k0 < K; k0 += TK) {
#pragma unroll
        for (int i = 0; i < 2; i++) {
            int idx = tid + i * 256;        // 0..511 float4 slots
            int r   = idx >> 2;             // 0..127
            int kc  = (idx & 3) << 2;       // 0,4,8,12
            float4 a4 = *(const float4*)&A[(size_t)(bm + r) * K + k0 + kc];
            As[kc+0][r] = a4.x; As[kc+1][r] = a4.y;
            As[kc+2][r] = a4.z; As[kc+3][r] = a4.w;
            float4 b4 = *(const float4*)&B[(size_t)(bn + r) * K + k0 + kc];
            Bs[kc+0][r] = b4.x; Bs[kc+1][r] = b4.y;
            Bs[kc+2][r] = b4.z; Bs[kc+3][r] = b4.w;
        }
        __syncthreads();

#pragma unroll
        for (int kk = 0; kk < TK; kk++) {
            float a[8], b[8];
            *(float4*)&a[0] = *(const float4*)&As[kk][trow];
            *(float4*)&a[4] = *(const float4*)&As[kk][trow + 4];
            *(float4*)&b[0] = *(const float4*)&Bs[kk][tcol];
            *(float4*)&b[4] = *(const float4*)&Bs[kk][tcol + 4];
#pragma unroll
            for (int i = 0; i < 8; i++)
#pragma unroll
                for (int j = 0; j < 8; j++)
                    acc[i][j] = fmaf(a[i], b[j], acc[i][j]);
        }
        __syncthreads();
    }

#pragma unroll
    for (int i = 0; i < 8; i++) {
        float* cp = &C[(size_t)(bm + trow + i) * N + bn + tcol];
        float4 c0 = make_float4(acc[i][0], acc[i][1], acc[i][2], acc[i][3]);
        float4 c1 = make_float4(acc[i][4], acc[i][5], acc[i][6], acc[i][7]);
        *(float4*)&cp[0] = c0;
        *(float4*)&cp[4] = c1;
    }
}

// ---------------------------------------------------------------------------
// Flash attention (fp32, causal, GQA ratio 4).
// Block: 256 threads (8 warps). Tile: 64 q rows x 64 kv cols, head dim 64.
// Warp w owns q rows [w*8, w*8+8). Lane owns kv cols / dims {lane, lane+32}.
// Static smem: Qs 16K + Ks 16K + Vs 16K = 48KB. PV uses warp shuffles.
// ---------------------------------------------------------------------------
#define BM 64
#define BN 64

__global__ __launch_bounds__(256, 2)
void attn_kernel(const float* __restrict__ Q, const float* __restrict__ Kg,
                 const float* __restrict__ Vg, float* __restrict__ O)
{
    __shared__ float Qs[BM * HD];        // [row][d]
    __shared__ float Ks[HD * BN];        // transposed: [d][n]
    __shared__ float Vs[BN * HD];        // [n][d]

    const int b     = blockIdx.z;
    const int h     = blockIdx.y;
    const int qtile = blockIdx.x;
    const int tid   = threadIdx.x;
    const int lane  = tid & 31;
    const int w     = tid >> 5;
    const int kvh   = h >> 2;            // GQA ratio = 4
    const float scale = 0.125f;          // 64^-0.5

    const int qBase   = qtile * BM;
    const int rowBase = w * 8;

    // Load Q tile (64 x 64)
    for (int i = tid; i < BM * HD / 4; i += 256) {
        int r  = i >> 4;              // / (HD/4)
        int dc = (i & 15) << 2;
        float4 v = *(const float4*)&Q[(size_t)(b * SEQ + qBase + r) * DIM + h * HD + dc];
        *(float4*)&Qs[r * HD + dc] = v;
    }

    float o0[8], o1[8], mrow[8], lrow[8];
#pragma unroll
    for (int r = 0; r < 8; r++) {
        o0[r] = 0.f; o1[r] = 0.f; mrow[r] = -1e30f; lrow[r] = 0.f;
    }

    const int ntiles = qtile + 1;
    for (int j = 0; j < ntiles; j++) {
        const int kvBase = j * BN;
        __syncthreads();
        // Load K (transposed) and V tiles
        for (int i = tid; i < BN * HD / 4; i += 256) {
            int n  = i >> 4;
            int dc = (i & 15) << 2;
            size_t base = (size_t)(b * SEQ + kvBase + n) * KVD + kvh * HD + dc;
            float4 k4 = *(const float4*)&Kg[base];
            Ks[(dc + 0) * BN + n] = k4.x;
            Ks[(dc + 1) * BN + n] = k4.y;
            Ks[(dc + 2) * BN + n] = k4.z;
            Ks[(dc + 3) * BN + n] = k4.w;
            float4 v4 = *(const float4*)&Vg[base];
            *(float4*)&Vs[n * HD + dc] = v4;
        }
        __syncthreads();

        // S = Q * K^T  (per-warp 8x64 fragment; lane owns cols lane, lane+32)
        float s0[8], s1[8];
#pragma unroll
        for (int r = 0; r < 8; r++) { s0[r] = 0.f; s1[r] = 0.f; }

        for (int d4 = 0; d4 < HD; d4 += 4) {
            float k0v[4], k1v[4];
#pragma unroll
            for (int q = 0; q < 4; q++) {
                k0v[q] = Ks[(d4 + q) * BN + lane];
                k1v[q] = Ks[(d4 + q) * BN + lane + 32];
            }
#pragma unroll
            for (int r = 0; r < 8; r++) {
                float4 q4 = *(const float4*)&Qs[(rowBase + r) * HD + d4];
                s0[r] = fmaf(q4.x, k0v[0], s0[r]);
                s0[r] = fmaf(q4.y, k0v[1], s0[r]);
                s0[r] = fmaf(q4.z, k0v[2], s0[r]);
                s0[r] = fmaf(q4.w, k0v[3], s0[r]);
                s1[r] = fmaf(q4.x, k1v[0], s1[r]);
                s1[r] = fmaf(q4.y, k1v[1], s1[r]);
                s1[r] = fmaf(q4.z, k1v[2], s1[r]);
                s1[r] = fmaf(q4.w, k1v[3], s1[r]);
            }
        }

        // Online softmax (per row); s0/s1 become P values
        const bool diag = (j == qtile);
#pragma unroll
        for (int r = 0; r < 8; r++) {
            int qi = qBase + rowBase + r;
            float v0 = s0[r] * scale;
            float v1 = s1[r] * scale;
            if (diag) {
                if (kvBase + lane      > qi) v0 = -1e30f;
                if (kvBase + lane + 32 > qi) v1 = -1e30f;
            }
            float mx = fmaxf(v0, v1);
#pragma unroll
            for (int off = 16; off > 0; off >>= 1)
                mx = fmaxf(mx, __shfl_xor_sync(0xffffffffu, mx, off));
            float mnew = fmaxf(mrow[r], mx);
            float p0 = __expf(v0 - mnew);
            float p1 = __expf(v1 - mnew);
            float ps = p0 + p1;
#pragma unroll
            for (int off = 16; off > 0; off >>= 1)
                ps += __shfl_xor_sync(0xffffffffu, ps, off);
            float alpha = __expf(mrow[r] - mnew);
            mrow[r] = mnew;
            lrow[r] = lrow[r] * alpha + ps;
            o0[r] *= alpha;
            o1[r] *= alpha;
            s0[r] = p0;   // reuse as P
            s1[r] = p1;
        }

        // O += P * V   (P distributed across lanes by n; broadcast via shuffle)
#pragma unroll 4
        for (int n = 0; n < 32; n++) {
            float v0 = Vs[n * HD + lane];
            float v1 = Vs[n * HD + lane + 32];
#pragma unroll
            for (int r = 0; r < 8; r++) {
                float p = __shfl_sync(0xffffffffu, s0[r], n);
                o0[r] = fmaf(p, v0, o0[r]);
                o1[r] = fmaf(p, v1, o1[r]);
            }
        }
#pragma unroll 4
        for (int n = 0; n < 32; n++) {
            float v0 = Vs[(n + 32) * HD + lane];
            float v1 = Vs[(n + 32) * HD + lane + 32];
#pragma unroll
            for (int r = 0; r < 8; r++) {
                float p = __shfl_sync(0xffffffffu, s1[r], n);
                o0[r] = fmaf(p, v0, o0[r]);
                o1[r] = fmaf(p, v1, o1[r]);
            }
        }
    }

    // Epilogue: normalize and store
#pragma unroll
    for (int r = 0; r < 8; r++) {
        float inv = 1.f / lrow[r];
        int qi = qBase + rowBase + r;
        float* op = &O[(size_t)(b * SEQ + qi) * DIM + h * HD];
        op[lane]      = o0[r] * inv;
        op[lane + 32] = o1[r] * inv;
    }
}

// ---------------------------------------------------------------------------
// Launch
// ---------------------------------------------------------------------------
extern "C" void kernel_launch(void* const* d_in, const int* in_sizes, int n_in,
                              void* d_out, int out_size)
{
    const float* x  = (const float*)d_in[0];
    const float* wq = (const float*)d_in[1];
    const float* wk = (const float*)d_in[2];
    const float* wv = (const float*)d_in[3];
    const float* wo = (const float*)d_in[4];
    float* out = (float*)d_out;

    float *pQ, *pK, *pV, *pAO;
    cudaGetSymbolAddress((void**)&pQ,  g_Q);
    cudaGetSymbolAddress((void**)&pK,  g_K);
    cudaGetSymbolAddress((void**)&pV,  g_V);
    cudaGetSymbolAddress((void**)&pAO, g_AO);

    dim3 blk(256);
    // Projections
    gemm_nt<<<dim3(DIM / GT, MTOT / GT), blk>>>(x, wq, pQ, MTOT, DIM, DIM);
    gemm_nt<<<dim3(KVD / GT, MTOT / GT), blk>>>(x, wk, pK, MTOT, KVD, DIM);
    gemm_nt<<<dim3(KVD / GT, MTOT / GT), blk>>>(x, wv, pV, MTOT, KVD, DIM);
    // Attention
    attn_kernel<<<dim3(SEQ / BM, NH, BATCH), blk>>>(pQ, pK, pV, pAO);
    // Output projection
    gemm_nt<<<dim3(DIM / GT, MTOT / GT), blk>>>(pAO, wo, out, MTOT, DIM, DIM);
}

// round 3
// speedup vs baseline: 1.4651x; 1.4651x over previous
#include <cuda_runtime.h>
#include <cuda_bf16.h>
#include <cstdint>
#include <math.h>

// Problem constants
#define BATCH 2
#define SEQ   2048
#define DIM   2048
#define NH    32
#define NKV   8
#define HD    64
#define KVD   (NKV*HD)    // 512
#define MTOT  (BATCH*SEQ) // 4096

// Scratch (device globals: allocation-free)
__device__ float g_Q [MTOT * DIM];
__device__ float g_K [MTOT * KVD];
__device__ float g_V [MTOT * KVD];
__device__ float g_AO[MTOT * DIM];

// ============================ helpers ======================================
__device__ __forceinline__ uint32_t smem_u32(const void* p) {
    uint32_t a;
    asm("{ .reg .u64 t; cvta.to.shared.u64 t, %1; cvt.u32.u64 %0, t; }"
        : "=r"(a) : "l"(p));
    return a;
}

__device__ __forceinline__ void ldmatrix_x4(uint32_t& r0, uint32_t& r1,
                                            uint32_t& r2, uint32_t& r3,
                                            uint32_t addr) {
    asm volatile("ldmatrix.sync.aligned.m8n8.x4.shared.b16 {%0,%1,%2,%3}, [%4];"
                 : "=r"(r0), "=r"(r1), "=r"(r2), "=r"(r3) : "r"(addr));
}

__device__ __forceinline__ void mma_bf16(float* d, const uint32_t* a,
                                         const uint32_t* b) {
    asm volatile(
        "mma.sync.aligned.m16n8k16.row.col.f32.bf16.bf16.f32 "
        "{%0,%1,%2,%3}, {%4,%5,%6,%7}, {%8,%9}, {%0,%1,%2,%3};"
        : "+f"(d[0]), "+f"(d[1]), "+f"(d[2]), "+f"(d[3])
        : "r"(a[0]), "r"(a[1]), "r"(a[2]), "r"(a[3]), "r"(b[0]), "r"(b[1]));
}

// ===================== split-bf16 mma.sync GEMM ============================
// C[M,N] = A[M,K] @ B[N,K]^T (fp32 row-major). M%128==0, N%128==0, K%32==0.
// fp32 emulated as Ahi*Bhi + Ahi*Blo + Alo*Bhi with fp32 accumulation.
#define BK   32
#define LDS_ 40      // bf16 elements per smem row (32 + 8 pad); 80B, 16B-mult

__shared__ __align__(16) __nv_bfloat16 sAh[128 * LDS_];
__shared__ __align__(16) __nv_bfloat16 sAl[128 * LDS_];
__shared__ __align__(16) __nv_bfloat16 sBh[128 * LDS_];
__shared__ __align__(16) __nv_bfloat16 sBl[128 * LDS_];

__device__ __forceinline__ void cvt_store(__nv_bfloat16* hi, __nv_bfloat16* lo,
                                          int off, float4 v) {
    float f[4] = {v.x, v.y, v.z, v.w};
    unsigned short hb[4], lb[4];
#pragma unroll
    for (int j = 0; j < 4; j++) {
        __nv_bfloat16 h = __float2bfloat16(f[j]);
        __nv_bfloat16 l = __float2bfloat16(f[j] - __bfloat162float(h));
        hb[j] = __bfloat16_as_ushort(h);
        lb[j] = __bfloat16_as_ushort(l);
    }
    *(uint2*)&hi[off] = make_uint2(hb[0] | ((uint32_t)hb[1] << 16),
                                   hb[2] | ((uint32_t)hb[3] << 16));
    *(uint2*)&lo[off] = make_uint2(lb[0] | ((uint32_t)lb[1] << 16),
                                   lb[2] | ((uint32_t)lb[3] << 16));
}

__global__ __launch_bounds__(256, 1)
void gemm_mma(const float* __restrict__ A, const float* __restrict__ B,
              float* __restrict__ C, int M, int N, int K)
{
    const int tid  = threadIdx.x;
    const int lane = tid & 31;
    const int wid  = tid >> 5;
    const int wm   = wid & 1;        // 2 warp-rows   (64 M each)
    const int wn   = wid >> 1;       // 4 warp-cols   (32 N each)
    const int bm   = blockIdx.y * 128;
    const int bn   = blockIdx.x * 128;

    float acc[4][4][4];
#pragma unroll
    for (int i = 0; i < 4; i++)
#pragma unroll
        for (int j = 0; j < 4; j++)
#pragma unroll
            for (int q = 0; q < 4; q++) acc[i][j][q] = 0.f;

    // smem byte bases (for ldmatrix)
    const uint32_t uAh = smem_u32(sAh), uAl = smem_u32(sAl);
    const uint32_t uBh = smem_u32(sBh), uBl = smem_u32(sBl);

    // ldmatrix lane address components (in bf16 elements)
    // A: lane L -> row (lane%16), k-half (lane/16)*8
    const int aRow  = lane & 15;
    const int aKoff = (lane >> 4) << 3;
    const int aBase = (wm * 64 + aRow) * LDS_ + aKoff;
    // B (two n-blocks per x4): lane L -> n = 8*(L/16) + L%8, k-half = ((L/8)&1)*8
    const int bN    = ((lane >> 4) << 3) + (lane & 7);
    const int bKoff = ((lane >> 3) & 1) << 3;
    const int bBase = (wn * 32 + bN) * LDS_ + bKoff;

    // global load slots: s = tid + 256*j; row = s/8, col4 = (s%8)*4
    int gr[4], gc[4], soff[4];
#pragma unroll
    for (int j = 0; j < 4; j++) {
        int s = tid + (j << 8);
        gr[j] = s >> 3;
        gc[j] = (s & 7) << 2;
        soff[j] = gr[j] * LDS_ + gc[j];
    }

    float4 pa[4], pb[4];
#pragma unroll
    for (int j = 0; j < 4; j++) {
        pa[j] = *(const float4*)&A[(size_t)(bm + gr[j]) * K + gc[j]];
        pb[j] = *(const float4*)&B[(size_t)(bn + gr[j]) * K + gc[j]];
    }

    const int NC = K / BK;
    for (int c = 0; c < NC; c++) {
#pragma unroll
        for (int j = 0; j < 4; j++) {
            cvt_store(sAh, sAl, soff[j], pa[j]);
            cvt_store(sBh, sBl, soff[j], pb[j]);
        }
        __syncthreads();

        if (c + 1 < NC) {
            const int k0 = (c + 1) * BK;
#pragma unroll
            for (int j = 0; j < 4; j++) {
                pa[j] = *(const float4*)&A[(size_t)(bm + gr[j]) * K + k0 + gc[j]];
                pb[j] = *(const float4*)&B[(size_t)(bn + gr[j]) * K + k0 + gc[j]];
            }
        }

#pragma unroll
        for (int kk = 0; kk < 2; kk++) {        // two k16 steps in BK=32
            const int ke = kk << 4;
            // B fragments: 4 n-blocks, hi & lo (2 x4-ldmatrix each)
            uint32_t bh[4][2], bl[4][2];
#pragma unroll
            for (int g = 0; g < 2; g++) {       // n-block pairs (0,1) and (2,3)
                uint32_t addr = (uint32_t)((bBase + g * 16 * LDS_ + ke) * 2);
                ldmatrix_x4(bh[g*2][0], bh[g*2][1], bh[g*2+1][0], bh[g*2+1][1],
                            uBh + addr);
                ldmatrix_x4(bl[g*2][0], bl[g*2][1], bl[g*2+1][0], bl[g*2+1][1],
                            uBl + addr);
            }
#pragma unroll
            for (int mi = 0; mi < 4; mi++) {
                uint32_t ah[4], al[4];
                uint32_t addr = (uint32_t)((aBase + mi * 16 * LDS_ + ke) * 2);
                ldmatrix_x4(ah[0], ah[1], ah[2], ah[3], uAh + addr);
                ldmatrix_x4(al[0], al[1], al[2], al[3], uAl + addr);
#pragma unroll
                for (int ni = 0; ni < 4; ni++) {
                    mma_bf16(acc[mi][ni], ah, bh[ni]);
                    mma_bf16(acc[mi][ni], ah, bl[ni]);
                    mma_bf16(acc[mi][ni], al, bh[ni]);
                }
            }
        }
        __syncthreads();
    }

    // Epilogue: D fragment (row = lane/4 [+8], col = 2*(lane%4) +{0,1})
    const int erow = lane >> 2;
    const int ecol = (lane & 3) << 1;
#pragma unroll
    for (int mi = 0; mi < 4; mi++) {
#pragma unroll
        for (int ni = 0; ni < 4; ni++) {
            int r0 = bm + wm * 64 + mi * 16 + erow;
            int cc = bn + wn * 32 + ni * 8 + ecol;
            *(float2*)&C[(size_t)r0 * N + cc] =
                make_float2(acc[mi][ni][0], acc[mi][ni][1]);
            *(float2*)&C[(size_t)(r0 + 8) * N + cc] =
                make_float2(acc[mi][ni][2], acc[mi][ni][3]);
        }
    }
}

// ======================= Flash attention (fp32 SIMT) =======================
#define BM 64
#define BN 64

__global__ __launch_bounds__(256, 2)
void attn_kernel(const float* __restrict__ Q, const float* __restrict__ Kg,
                 const float* __restrict__ Vg, float* __restrict__ O)
{
    __shared__ float Qs[BM * HD];
    __shared__ float Ks[HD * BN];
    __shared__ float Vs[BN * HD];

    const int b     = blockIdx.z;
    const int h     = blockIdx.y;
    const int qtile = blockIdx.x;
    const int tid   = threadIdx.x;
    const int lane  = tid & 31;
    const int w     = tid >> 5;
    const int kvh   = h >> 2;
    const float scale = 0.125f;

    const int qBase   = qtile * BM;
    const int rowBase = w * 8;

    for (int i = tid; i < BM * HD / 4; i += 256) {
        int r  = i >> 4;
        int dc = (i & 15) << 2;
        float4 v = *(const float4*)&Q[(size_t)(b * SEQ + qBase + r) * DIM + h * HD + dc];
        *(float4*)&Qs[r * HD + dc] = v;
    }

    float o0[8], o1[8], mrow[8], lrow[8];
#pragma unroll
    for (int r = 0; r < 8; r++) {
        o0[r] = 0.f; o1[r] = 0.f; mrow[r] = -1e30f; lrow[r] = 0.f;
    }

    const int ntiles = qtile + 1;
    for (int j = 0; j < ntiles; j++) {
        const int kvBase = j * BN;
        __syncthreads();
        for (int i = tid; i < BN * HD / 4; i += 256) {
            int n  = i >> 4;
            int dc = (i & 15) << 2;
            size_t base = (size_t)(b * SEQ + kvBase + n) * KVD + kvh * HD + dc;
            float4 k4 = *(const float4*)&Kg[base];
            Ks[(dc + 0) * BN + n] = k4.x;
            Ks[(dc + 1) * BN + n] = k4.y;
            Ks[(dc + 2) * BN + n] = k4.z;
            Ks[(dc + 3) * BN + n] = k4.w;
            float4 v4 = *(const float4*)&Vg[base];
            *(float4*)&Vs[n * HD + dc] = v4;
        }
        __syncthreads();

        float s0[8], s1[8];
#pragma unroll
        for (int r = 0; r < 8; r++) { s0[r] = 0.f; s1[r] = 0.f; }

        for (int d4 = 0; d4 < HD; d4 += 4) {
            float k0v[4], k1v[4];
#pragma unroll
            for (int q = 0; q < 4; q++) {
                k0v[q] = Ks[(d4 + q) * BN + lane];
                k1v[q] = Ks[(d4 + q) * BN + lane + 32];
            }
#pragma unroll
            for (int r = 0; r < 8; r++) {
                float4 q4 = *(const float4*)&Qs[(rowBase + r) * HD + d4];
                s0[r] = fmaf(q4.x, k0v[0], s0[r]);
                s0[r] = fmaf(q4.y, k0v[1], s0[r]);
                s0[r] = fmaf(q4.z, k0v[2], s0[r]);
                s0[r] = fmaf(q4.w, k0v[3], s0[r]);
                s1[r] = fmaf(q4.x, k1v[0], s1[r]);
                s1[r] = fmaf(q4.y, k1v[1], s1[r]);
                s1[r] = fmaf(q4.z, k1v[2], s1[r]);
                s1[r] = fmaf(q4.w, k1v[3], s1[r]);
            }
        }

        const bool diag = (j == qtile);
#pragma unroll
        for (int r = 0; r < 8; r++) {
            int qi = qBase + rowBase + r;
            float v0 = s0[r] * scale;
            float v1 = s1[r] * scale;
            if (diag) {
                if (kvBase + lane      > qi) v0 = -1e30f;
                if (kvBase + lane + 32 > qi) v1 = -1e30f;
            }
            float mx = fmaxf(v0, v1);
#pragma unroll
            for (int off = 16; off > 0; off >>= 1)
                mx = fmaxf(mx, __shfl_xor_sync(0xffffffffu, mx, off));
            float mnew = fmaxf(mrow[r], mx);
            float p0 = __expf(v0 - mnew);
            float p1 = __expf(v1 - mnew);
            float ps = p0 + p1;
#pragma unroll
            for (int off = 16; off > 0; off >>= 1)
                ps += __shfl_xor_sync(0xffffffffu, ps, off);
            float alpha = __expf(mrow[r] - mnew);
            mrow[r] = mnew;
            lrow[r] = lrow[r] * alpha + ps;
            o0[r] *= alpha;
            o1[r] *= alpha;
            s0[r] = p0;
            s1[r] = p1;
        }

#pragma unroll 4
        for (int n = 0; n < 32; n++) {
            float v0 = Vs[n * HD + lane];
            float v1 = Vs[n * HD + lane + 32];
#pragma unroll
            for (int r = 0; r < 8; r++) {
                float p = __shfl_sync(0xffffffffu, s0[r], n);
                o0[r] = fmaf(p, v0, o0[r]);
                o1[r] = fmaf(p, v1, o1[r]);
            }
        }
#pragma unroll 4
        for (int n = 0; n < 32; n++) {
            float v0 = Vs[(n + 32) * HD + lane];
            float v1 = Vs[(n + 32) * HD + lane + 32];
#pragma unroll
            for (int r = 0; r < 8; r++) {
                float p = __shfl_sync(0xffffffffu, s1[r], n);
                o0[r] = fmaf(p, v0, o0[r]);
                o1[r] = fmaf(p, v1, o1[r]);
            }
        }
    }

#pragma unroll
    for (int r = 0; r < 8; r++) {
        float inv = 1.f / lrow[r];
        int qi = qBase + rowBase + r;
        float* op = &O[(size_t)(b * SEQ + qi) * DIM + h * HD];
        op[lane]      = o0[r] * inv;
        op[lane + 32] = o1[r] * inv;
    }
}

// =============================== Launch ====================================
extern "C" void kernel_launch(void* const* d_in, const int* in_sizes, int n_in,
                              void* d_out, int out_size)
{
    const float* x  = (const float*)d_in[0];
    const float* wq = (const float*)d_in[1];
    const float* wk = (const float*)d_in[2];
    const float* wv = (const float*)d_in[3];
    const float* wo = (const float*)d_in[4];
    float* out = (float*)d_out;

    float *pQ, *pK, *pV, *pAO;
    cudaGetSymbolAddress((void**)&pQ,  g_Q);
    cudaGetSymbolAddress((void**)&pK,  g_K);
    cudaGetSymbolAddress((void**)&pV,  g_V);
    cudaGetSymbolAddress((void**)&pAO, g_AO);

    dim3 blk(256);
    gemm_mma<<<dim3(DIM / 128, MTOT / 128), blk>>>(x, wq, pQ, MTOT, DIM, DIM);
    gemm_mma<<<dim3(KVD / 128, MTOT / 128), blk>>>(x, wk, pK, MTOT, KVD, DIM);
    gemm_mma<<<dim3(KVD / 128, MTOT / 128), blk>>>(x, wv, pV, MTOT, KVD, DIM);
    attn_kernel<<<dim3(SEQ / BM, NH, BATCH), blk>>>(pQ, pK, pV, pAO);
    gemm_mma<<<dim3(DIM / 128, MTOT / 128), blk>>>(pAO, wo, out, MTOT, DIM, DIM);
}

// round 4
// speedup vs baseline: 2.4198x; 1.6516x over previous
#include <cuda_runtime.h>
#include <cuda_bf16.h>
#include <cstdint>
#include <math.h>

// Problem constants
#define BATCH 2
#define SEQ   2048
#define DIM   2048
#define NH    32
#define NKV   8
#define HD    64
#define KVD   (NKV*HD)    // 512
#define MTOT  (BATCH*SEQ) // 4096

// Scratch (device globals: allocation-free)
__device__ float g_Q [MTOT * DIM];
__device__ float g_K [MTOT * KVD];
__device__ float g_V [MTOT * KVD];
__device__ float g_AO[MTOT * DIM];

// ============================ helpers ======================================
__device__ __forceinline__ uint32_t smem_u32(const void* p) {
    uint32_t a;
    asm("{ .reg .u64 t; cvta.to.shared.u64 t, %1; cvt.u32.u64 %0, t; }"
        : "=r"(a) : "l"(p));
    return a;
}

__device__ __forceinline__ void ldmatrix_x4(uint32_t& r0, uint32_t& r1,
                                            uint32_t& r2, uint32_t& r3,
                                            uint32_t addr) {
    asm volatile("ldmatrix.sync.aligned.m8n8.x4.shared.b16 {%0,%1,%2,%3}, [%4];"
                 : "=r"(r0), "=r"(r1), "=r"(r2), "=r"(r3) : "r"(addr));
}
__device__ __forceinline__ void ldmatrix_x4_trans(uint32_t& r0, uint32_t& r1,
                                                  uint32_t& r2, uint32_t& r3,
                                                  uint32_t addr) {
    asm volatile("ldmatrix.sync.aligned.m8n8.x4.trans.shared.b16 {%0,%1,%2,%3}, [%4];"
                 : "=r"(r0), "=r"(r1), "=r"(r2), "=r"(r3) : "r"(addr));
}

__device__ __forceinline__ void mma_bf16(float* d, const uint32_t* a,
                                         const uint32_t* b) {
    asm volatile(
        "mma.sync.aligned.m16n8k16.row.col.f32.bf16.bf16.f32 "
        "{%0,%1,%2,%3}, {%4,%5,%6,%7}, {%8,%9}, {%0,%1,%2,%3};"
        : "+f"(d[0]), "+f"(d[1]), "+f"(d[2]), "+f"(d[3])
        : "r"(a[0]), "r"(a[1]), "r"(a[2]), "r"(a[3]), "r"(b[0]), "r"(b[1]));
}

// fp32 -> (hi,lo) bf16 split, packed pairs [lo-half = first element]
__device__ __forceinline__ void split2(float a, float b, uint32_t& hi, uint32_t& lo) {
    __nv_bfloat16 ha = __float2bfloat16(a), hb = __float2bfloat16(b);
    hi = (uint32_t)__bfloat16_as_ushort(ha) |
         ((uint32_t)__bfloat16_as_ushort(hb) << 16);
    float ra = a - __bfloat162float(ha);
    float rb = b - __bfloat162float(hb);
    uint32_t d;
    asm("cvt.rn.bf16x2.f32 %0, %1, %2;" : "=r"(d) : "f"(rb), "f"(ra));
    lo = d;
}

// exp(x*0.125) via 2^y polynomial on FMA pipe (avoids MUFU; x <= 0)
__device__ __forceinline__ float fexp2c(float x) {
    float y = fmaxf(x * 0.1803368801f, -126.f);   // 0.125 * log2(e)
    float r = rintf(y);
    float f = y - r;
    float p = 1.3333558e-3f;
    p = fmaf(p, f, 9.6181291e-3f);
    p = fmaf(p, f, 5.5504109e-2f);
    p = fmaf(p, f, 2.4022651e-1f);
    p = fmaf(p, f, 6.9314718e-1f);
    p = fmaf(p, f, 1.0f);
    return p * __int_as_float(((int)r + 127) << 23);
}

// ===================== split-bf16 mma.sync GEMM ============================
#define BK   32
#define LDS_ 40

__shared__ __align__(16) __nv_bfloat16 sAh[128 * LDS_];
__shared__ __align__(16) __nv_bfloat16 sAl[128 * LDS_];
__shared__ __align__(16) __nv_bfloat16 sBh[128 * LDS_];
__shared__ __align__(16) __nv_bfloat16 sBl[128 * LDS_];

__device__ __forceinline__ void cvt_store(__nv_bfloat16* hi, __nv_bfloat16* lo,
                                          int off, float4 v) {
    float f[4] = {v.x, v.y, v.z, v.w};
    unsigned short hb[4], lb[4];
#pragma unroll
    for (int j = 0; j < 4; j++) {
        __nv_bfloat16 h = __float2bfloat16(f[j]);
        __nv_bfloat16 l = __float2bfloat16(f[j] - __bfloat162float(h));
        hb[j] = __bfloat16_as_ushort(h);
        lb[j] = __bfloat16_as_ushort(l);
    }
    *(uint2*)&hi[off] = make_uint2(hb[0] | ((uint32_t)hb[1] << 16),
                                   hb[2] | ((uint32_t)hb[3] << 16));
    *(uint2*)&lo[off] = make_uint2(lb[0] | ((uint32_t)lb[1] << 16),
                                   lb[2] | ((uint32_t)lb[3] << 16));
}

__global__ __launch_bounds__(256, 1)
void gemm_mma(const float* __restrict__ A, const float* __restrict__ B,
              float* __restrict__ C, int M, int N, int K)
{
    const int tid  = threadIdx.x;
    const int lane = tid & 31;
    const int wid  = tid >> 5;
    const int wm   = wid & 1;
    const int wn   = wid >> 1;
    const int bm   = blockIdx.y * 128;
    const int bn   = blockIdx.x * 128;

    float acc[4][4][4];
#pragma unroll
    for (int i = 0; i < 4; i++)
#pragma unroll
        for (int j = 0; j < 4; j++)
#pragma unroll
            for (int q = 0; q < 4; q++) acc[i][j][q] = 0.f;

    const uint32_t uAh = smem_u32(sAh), uAl = smem_u32(sAl);
    const uint32_t uBh = smem_u32(sBh), uBl = smem_u32(sBl);

    const int aRow  = lane & 15;
    const int aKoff = (lane >> 4) << 3;
    const int aBase = (wm * 64 + aRow) * LDS_ + aKoff;
    const int bN    = ((lane >> 4) << 3) + (lane & 7);
    const int bKoff = ((lane >> 3) & 1) << 3;
    const int bBase = (wn * 32 + bN) * LDS_ + bKoff;

    int gr[4], gc[4], soff[4];
#pragma unroll
    for (int j = 0; j < 4; j++) {
        int s = tid + (j << 8);
        gr[j] = s >> 3;
        gc[j] = (s & 7) << 2;
        soff[j] = gr[j] * LDS_ + gc[j];
    }

    float4 pa[4], pb[4];
#pragma unroll
    for (int j = 0; j < 4; j++) {
        pa[j] = *(const float4*)&A[(size_t)(bm + gr[j]) * K + gc[j]];
        pb[j] = *(const float4*)&B[(size_t)(bn + gr[j]) * K + gc[j]];
    }

    const int NC = K / BK;
    for (int c = 0; c < NC; c++) {
#pragma unroll
        for (int j = 0; j < 4; j++) {
            cvt_store(sAh, sAl, soff[j], pa[j]);
            cvt_store(sBh, sBl, soff[j], pb[j]);
        }
        __syncthreads();

        if (c + 1 < NC) {
            const int k0 = (c + 1) * BK;
#pragma unroll
            for (int j = 0; j < 4; j++) {
                pa[j] = *(const float4*)&A[(size_t)(bm + gr[j]) * K + k0 + gc[j]];
                pb[j] = *(const float4*)&B[(size_t)(bn + gr[j]) * K + k0 + gc[j]];
            }
        }

#pragma unroll
        for (int kk = 0; kk < 2; kk++) {
            const int ke = kk << 4;
            uint32_t bh[4][2], bl[4][2];
#pragma unroll
            for (int g = 0; g < 2; g++) {
                uint32_t addr = (uint32_t)((bBase + g * 16 * LDS_ + ke) * 2);
                ldmatrix_x4(bh[g*2][0], bh[g*2][1], bh[g*2+1][0], bh[g*2+1][1],
                            uBh + addr);
                ldmatrix_x4(bl[g*2][0], bl[g*2][1], bl[g*2+1][0], bl[g*2+1][1],
                            uBl + addr);
            }
#pragma unroll
            for (int mi = 0; mi < 4; mi++) {
                uint32_t ah[4], al[4];
                uint32_t addr = (uint32_t)((aBase + mi * 16 * LDS_ + ke) * 2);
                ldmatrix_x4(ah[0], ah[1], ah[2], ah[3], uAh + addr);
                ldmatrix_x4(al[0], al[1], al[2], al[3], uAl + addr);
#pragma unroll
                for (int ni = 0; ni < 4; ni++) {
                    mma_bf16(acc[mi][ni], ah, bh[ni]);
                    mma_bf16(acc[mi][ni], ah, bl[ni]);
                    mma_bf16(acc[mi][ni], al, bh[ni]);
                }
            }
        }
        __syncthreads();
    }

    const int erow = lane >> 2;
    const int ecol = (lane & 3) << 1;
#pragma unroll
    for (int mi = 0; mi < 4; mi++) {
#pragma unroll
        for (int ni = 0; ni < 4; ni++) {
            int r0 = bm + wm * 64 + mi * 16 + erow;
            int cc = bn + wn * 32 + ni * 8 + ecol;
            *(float2*)&C[(size_t)r0 * N + cc] =
                make_float2(acc[mi][ni][0], acc[mi][ni][1]);
            *(float2*)&C[(size_t)(r0 + 8) * N + cc] =
                make_float2(acc[mi][ni][2], acc[mi][ni][3]);
        }
    }
}

// ================= Flash attention via split-bf16 mma.sync =================
// CTA: 256 thr (8 warps). Tile: 128 q-rows x 64 kv. Warp w: q rows [16w,16w+16).
#define LDQ 72
// smem (bf16 elems): Qh 9216 | Ql 9216 | Kh 4608 | Kl 4608 | Vh 4608 | Vl 4608
#define ATT_SMEM (36864 * 2)

__global__ __launch_bounds__(256, 1)
void attn_mma(const float* __restrict__ Q, const float* __restrict__ Kg,
              const float* __restrict__ Vg, float* __restrict__ O)
{
    extern __shared__ __nv_bfloat16 sm[];
    __nv_bfloat16* Qh = sm;
    __nv_bfloat16* Ql = sm + 9216;
    __nv_bfloat16* Kh = sm + 18432;
    __nv_bfloat16* Kl = sm + 23040;
    __nv_bfloat16* Vh = sm + 27648;
    __nv_bfloat16* Vl = sm + 32256;

    const int b = blockIdx.z, h = blockIdx.y, qt = blockIdx.x;
    const int tid = threadIdx.x, lane = tid & 31, w = tid >> 5;
    const int kvh = h >> 2;
    const int qBase = qt * 128;
    const int wq0 = qBase + 16 * w;     // warp's smallest q row

    // Load + split Q tile (128 x 64)
    for (int i = tid; i < 2048; i += 256) {
        int r = i >> 4, c4 = (i & 15) << 2;
        float4 v = *(const float4*)&Q[(size_t)(b*SEQ + qBase + r)*DIM + h*HD + c4];
        cvt_store(Qh, Ql, r * LDQ + c4, v);
    }
    __syncthreads();

    const uint32_t uQh = smem_u32(Qh), uQl = smem_u32(Ql);
    const uint32_t uKh = smem_u32(Kh), uKl = smem_u32(Kl);
    const uint32_t uVh = smem_u32(Vh), uVl = smem_u32(Vl);

    // Q fragments resident in registers for the whole kv loop
    uint32_t qh[4][4], ql[4][4];
    {
        int off0 = (16*w + (lane & 15)) * LDQ + ((lane >> 4) << 3);
#pragma unroll
        for (int kb = 0; kb < 4; kb++) {
            uint32_t off = (uint32_t)((off0 + kb * 16) * 2);
            ldmatrix_x4(qh[kb][0], qh[kb][1], qh[kb][2], qh[kb][3], uQh + off);
            ldmatrix_x4(ql[kb][0], ql[kb][1], ql[kb][2], ql[kb][3], uQl + off);
        }
    }

    float o[8][4];
#pragma unroll
    for (int nb = 0; nb < 8; nb++)
#pragma unroll
        for (int q = 0; q < 4; q++) o[nb][q] = 0.f;
    float m0 = -3e38f, m1 = -3e38f, l0 = 0.f, l1 = 0.f;

    const int bN = ((lane >> 4) << 3) + (lane & 7);
    const int bK = ((lane >> 3) & 1) << 3;
    const int vRow = lane & 15, vCol = (lane >> 4) << 3;
    const int r0   = lane >> 2;
    const int c2   = (lane & 3) << 1;
    const int qi0  = wq0 + r0, qi1 = qi0 + 8;
    const int ntiles = 2 * qt + 2;

    for (int j = 0; j < ntiles; j++) {
        const int kvBase = j * 64;
        __syncthreads();
        for (int i = tid; i < 1024; i += 256) {
            int r = i >> 4, c4 = (i & 15) << 2;
            size_t gb = (size_t)(b*SEQ + kvBase + r) * KVD + kvh*HD + c4;
            cvt_store(Kh, Kl, r * LDQ + c4, *(const float4*)&Kg[gb]);
            cvt_store(Vh, Vl, r * LDQ + c4, *(const float4*)&Vg[gb]);
        }
        __syncthreads();

        if (kvBase > wq0 + 15) continue;   // fully masked for this warp

        // ---- S = Q K^T (split 3-term) ----
        float sa[8][4];
#pragma unroll
        for (int nb = 0; nb < 8; nb++)
#pragma unroll
            for (int q = 0; q < 4; q++) sa[nb][q] = 0.f;

#pragma unroll
        for (int kb = 0; kb < 4; kb++) {
#pragma unroll
            for (int g = 0; g < 4; g++) {
                uint32_t off = (uint32_t)(((g*16 + bN) * LDQ + kb*16 + bK) * 2);
                uint32_t b0[2], b1[2], c0[2], c1[2];
                ldmatrix_x4(b0[0], b0[1], b1[0], b1[1], uKh + off);
                ldmatrix_x4(c0[0], c0[1], c1[0], c1[1], uKl + off);
                mma_bf16(sa[2*g],   qh[kb], b0);
                mma_bf16(sa[2*g],   qh[kb], c0);
                mma_bf16(sa[2*g],   ql[kb], b0);
                mma_bf16(sa[2*g+1], qh[kb], b1);
                mma_bf16(sa[2*g+1], qh[kb], c1);
                mma_bf16(sa[2*g+1], ql[kb], b1);
            }
        }

        // ---- causal mask (boundary tiles only) ----
        if (kvBase + 63 > wq0) {
#pragma unroll
            for (int nb = 0; nb < 8; nb++) {
                int col = kvBase + nb * 8 + c2;
                if (col     > qi0) sa[nb][0] = -3e38f;
                if (col + 1 > qi0) sa[nb][1] = -3e38f;
                if (col     > qi1) sa[nb][2] = -3e38f;
                if (col + 1 > qi1) sa[nb][3] = -3e38f;
            }
        }

        // ---- online softmax (FMA-pipe exp) ----
        float mx0 = -3e38f, mx1 = -3e38f;
#pragma unroll
        for (int nb = 0; nb < 8; nb++) {
            mx0 = fmaxf(mx0, fmaxf(sa[nb][0], sa[nb][1]));
            mx1 = fmaxf(mx1, fmaxf(sa[nb][2], sa[nb][3]));
        }
        mx0 = fmaxf(mx0, __shfl_xor_sync(0xffffffffu, mx0, 1));
        mx0 = fmaxf(mx0, __shfl_xor_sync(0xffffffffu, mx0, 2));
        mx1 = fmaxf(mx1, __shfl_xor_sync(0xffffffffu, mx1, 1));
        mx1 = fmaxf(mx1, __shfl_xor_sync(0xffffffffu, mx1, 2));
        float mn0 = fmaxf(m0, mx0), mn1 = fmaxf(m1, mx1);
        float a0 = fexp2c(m0 - mn0), a1 = fexp2c(m1 - mn1);
        m0 = mn0; m1 = mn1;

        float s0 = 0.f, s1 = 0.f;
#pragma unroll
        for (int nb = 0; nb < 8; nb++) {
            sa[nb][0] = fexp2c(sa[nb][0] - mn0); s0 += sa[nb][0];
            sa[nb][1] = fexp2c(sa[nb][1] - mn0); s0 += sa[nb][1];
            sa[nb][2] = fexp2c(sa[nb][2] - mn1); s1 += sa[nb][2];
            sa[nb][3] = fexp2c(sa[nb][3] - mn1); s1 += sa[nb][3];
        }
        s0 += __shfl_xor_sync(0xffffffffu, s0, 1);
        s0 += __shfl_xor_sync(0xffffffffu, s0, 2);
        s1 += __shfl_xor_sync(0xffffffffu, s1, 1);
        s1 += __shfl_xor_sync(0xffffffffu, s1, 2);
        l0 = l0 * a0 + s0;
        l1 = l1 * a1 + s1;
#pragma unroll
        for (int nb = 0; nb < 8; nb++) {
            o[nb][0] *= a0; o[nb][1] *= a0;
            o[nb][2] *= a1; o[nb][3] *= a1;
        }

        // ---- O += P V (P from S regs; split 3-term) ----
#pragma unroll
        for (int jk = 0; jk < 4; jk++) {
            uint32_t ph[4], pl[4];
            split2(sa[2*jk][0],   sa[2*jk][1],   ph[0], pl[0]);
            split2(sa[2*jk][2],   sa[2*jk][3],   ph[1], pl[1]);
            split2(sa[2*jk+1][0], sa[2*jk+1][1], ph[2], pl[2]);
            split2(sa[2*jk+1][2], sa[2*jk+1][3], ph[3], pl[3]);
#pragma unroll
            for (int g = 0; g < 4; g++) {
                uint32_t off = (uint32_t)(((jk*16 + vRow) * LDQ + g*16 + vCol) * 2);
                uint32_t vh0[2], vh1[2], vl0[2], vl1[2];
                ldmatrix_x4_trans(vh0[0], vh0[1], vh1[0], vh1[1], uVh + off);
                ldmatrix_x4_trans(vl0[0], vl0[1], vl1[0], vl1[1], uVl + off);
                mma_bf16(o[2*g],   ph, vh0);
                mma_bf16(o[2*g],   ph, vl0);
                mma_bf16(o[2*g],   pl, vh0);
                mma_bf16(o[2*g+1], ph, vh1);
                mma_bf16(o[2*g+1], ph, vl1);
                mma_bf16(o[2*g+1], pl, vh1);
            }
        }
    }

    // ---- epilogue ----
    float i0 = __fdividef(1.f, l0), i1 = __fdividef(1.f, l1);
#pragma unroll
    for (int nb = 0; nb < 8; nb++) {
        size_t base0 = (size_t)(b*SEQ + qi0) * DIM + h*HD + nb*8 + c2;
        *(float2*)&O[base0] = make_float2(o[nb][0] * i0, o[nb][1] * i0);
        *(float2*)&O[base0 + (size_t)8 * DIM] =
            make_float2(o[nb][2] * i1, o[nb][3] * i1);
    }
}

// =============================== Launch ====================================
extern "C" void kernel_launch(void* const* d_in, const int* in_sizes, int n_in,
                              void* d_out, int out_size)
{
    const float* x  = (const float*)d_in[0];
    const float* wq = (const float*)d_in[1];
    const float* wk = (const float*)d_in[2];
    const float* wv = (const float*)d_in[3];
    const float* wo = (const float*)d_in[4];
    float* out = (float*)d_out;

    float *pQ, *pK, *pV, *pAO;
    cudaGetSymbolAddress((void**)&pQ,  g_Q);
    cudaGetSymbolAddress((void**)&pK,  g_K);
    cudaGetSymbolAddress((void**)&pV,  g_V);
    cudaGetSymbolAddress((void**)&pAO, g_AO);

    cudaFuncSetAttribute(attn_mma, cudaFuncAttributeMaxDynamicSharedMemorySize,
                         ATT_SMEM);

    dim3 blk(256);
    gemm_mma<<<dim3(DIM / 128, MTOT / 128), blk>>>(x, wq, pQ, MTOT, DIM, DIM);
    gemm_mma<<<dim3(KVD / 128, MTOT / 128), blk>>>(x, wk, pK, MTOT, KVD, DIM);
    gemm_mma<<<dim3(KVD / 128, MTOT / 128), blk>>>(x, wv, pV, MTOT, KVD, DIM);
    attn_mma<<<dim3(SEQ / 128, NH, BATCH), blk, ATT_SMEM>>>(pQ, pK, pV, pAO);
    gemm_mma<<<dim3(DIM / 128, MTOT / 128), blk>>>(pAO, wo, out, MTOT, DIM, DIM);
}

// round 5
// speedup vs baseline: 3.1907x; 1.3186x over previous
#include <cuda_runtime.h>
#include <cuda_bf16.h>
#include <cstdint>
#include <math.h>

// Problem constants
#define BATCH 2
#define SEQ   2048
#define DIM   2048
#define NH    32
#define NKV   8
#define HD    64
#define KVD   (NKV*HD)    // 512
#define MTOT  (BATCH*SEQ) // 4096

// Scratch (device globals: allocation-free) — all pre-split bf16 pairs
__device__ __nv_bfloat16 g_xh [MTOT * DIM],  g_xl [MTOT * DIM];
__device__ __nv_bfloat16 g_wqh[DIM * DIM],   g_wql[DIM * DIM];
__device__ __nv_bfloat16 g_wkh[KVD * DIM],   g_wkl[KVD * DIM];
__device__ __nv_bfloat16 g_wvh[KVD * DIM],   g_wvl[KVD * DIM];
__device__ __nv_bfloat16 g_woh[DIM * DIM],   g_wol[DIM * DIM];
__device__ __nv_bfloat16 g_Qh [MTOT * DIM],  g_Ql [MTOT * DIM];
__device__ __nv_bfloat16 g_Kh [MTOT * KVD],  g_Kl [MTOT * KVD];
__device__ __nv_bfloat16 g_Vh [MTOT * KVD],  g_Vl [MTOT * KVD];
__device__ __nv_bfloat16 g_Oh [MTOT * DIM],  g_Ol [MTOT * DIM];

// ============================ helpers ======================================
__device__ __forceinline__ uint32_t smem_u32(const void* p) {
    uint32_t a;
    asm("{ .reg .u64 t; cvta.to.shared.u64 t, %1; cvt.u32.u64 %0, t; }"
        : "=r"(a) : "l"(p));
    return a;
}
__device__ __forceinline__ void cp16(uint32_t dst, const void* src) {
    asm volatile("cp.async.cg.shared.global [%0], [%1], 16;"
                 :: "r"(dst), "l"(src) : "memory");
}
#define CP_COMMIT() asm volatile("cp.async.commit_group;" ::: "memory")
#define CP_WAIT0()  asm volatile("cp.async.wait_group 0;" ::: "memory")
#define CP_WAIT1()  asm volatile("cp.async.wait_group 1;" ::: "memory")

__device__ __forceinline__ void ldmatrix_x4(uint32_t& r0, uint32_t& r1,
                                            uint32_t& r2, uint32_t& r3,
                                            uint32_t addr) {
    asm volatile("ldmatrix.sync.aligned.m8n8.x4.shared.b16 {%0,%1,%2,%3}, [%4];"
                 : "=r"(r0), "=r"(r1), "=r"(r2), "=r"(r3) : "r"(addr));
}
__device__ __forceinline__ void ldmatrix_x4_trans(uint32_t& r0, uint32_t& r1,
                                                  uint32_t& r2, uint32_t& r3,
                                                  uint32_t addr) {
    asm volatile("ldmatrix.sync.aligned.m8n8.x4.trans.shared.b16 {%0,%1,%2,%3}, [%4];"
                 : "=r"(r0), "=r"(r1), "=r"(r2), "=r"(r3) : "r"(addr));
}
__device__ __forceinline__ void mma_bf16(float* d, const uint32_t* a,
                                         const uint32_t* b) {
    asm volatile(
        "mma.sync.aligned.m16n8k16.row.col.f32.bf16.bf16.f32 "
        "{%0,%1,%2,%3}, {%4,%5,%6,%7}, {%8,%9}, {%0,%1,%2,%3};"
        : "+f"(d[0]), "+f"(d[1]), "+f"(d[2]), "+f"(d[3])
        : "r"(a[0]), "r"(a[1]), "r"(a[2]), "r"(a[3]), "r"(b[0]), "r"(b[1]));
}

// fp32 pair -> packed (hi,lo) bf16x2
__device__ __forceinline__ void split2(float a, float b, uint32_t& hi, uint32_t& lo) {
    __nv_bfloat16 ha = __float2bfloat16(a), hb = __float2bfloat16(b);
    hi = (uint32_t)__bfloat16_as_ushort(ha) |
         ((uint32_t)__bfloat16_as_ushort(hb) << 16);
    float ra = a - __bfloat162float(ha);
    float rb = b - __bfloat162float(hb);
    uint32_t d;
    asm("cvt.rn.bf16x2.f32 %0, %1, %2;" : "=r"(d) : "f"(rb), "f"(ra));
    lo = d;
}

// exp(x*0.125) via 2^y polynomial on FMA pipe (x <= 0)
__device__ __forceinline__ float fexp2c(float x) {
    float y = fmaxf(x * 0.1803368801f, -126.f);
    float r = rintf(y);
    float f = y - r;
    float p = 1.3333558e-3f;
    p = fmaf(p, f, 9.6181291e-3f);
    p = fmaf(p, f, 5.5504109e-2f);
    p = fmaf(p, f, 2.4022651e-1f);
    p = fmaf(p, f, 6.9314718e-1f);
    p = fmaf(p, f, 1.0f);
    return p * __int_as_float(((int)r + 127) << 23);
}

// ====================== pre-split kernel (fp32 -> hi/lo bf16) ==============
__global__ __launch_bounds__(256)
void split_f32(const float* __restrict__ in, __nv_bfloat16* __restrict__ hi,
               __nv_bfloat16* __restrict__ lo, int n4)
{
    int i = blockIdx.x * 256 + threadIdx.x;
    if (i >= n4) return;
    float4 v = ((const float4*)in)[i];
    uint32_t h0, l0, h1, l1;
    split2(v.x, v.y, h0, l0);
    split2(v.z, v.w, h1, l1);
    ((uint2*)hi)[i] = make_uint2(h0, h1);
    ((uint2*)lo)[i] = make_uint2(l0, l1);
}

// ===================== pre-split bf16 GEMM (cp.async pipelined) ============
// C[M,N] = A[M,K] @ B[N,K]^T. A,B pre-split bf16. 128x128x32 CTA tile.
#define LDS_ 40
// smem per stage (elems): Ah 5120 | Al 5120 | Bh 5120 | Bl 5120 = 20480
#define GSTG 20480
#define GEMM_SMEM (2 * GSTG * 2)   // bytes = 81920

template<int SPLIT>
__global__ __launch_bounds__(256, 2)
void gemm_ps(const __nv_bfloat16* __restrict__ Ah_g, const __nv_bfloat16* __restrict__ Al_g,
             const __nv_bfloat16* __restrict__ Bh_g, const __nv_bfloat16* __restrict__ Bl_g,
             float* __restrict__ C, __nv_bfloat16* __restrict__ Ch,
             __nv_bfloat16* __restrict__ Cl, int M, int N, int K)
{
    extern __shared__ __nv_bfloat16 gsm[];
    const uint32_t usm = smem_u32(gsm);
    const int tid  = threadIdx.x;
    const int lane = tid & 31;
    const int wid  = tid >> 5;
    const int wm   = wid & 1;
    const int wn   = wid >> 1;
    const int bm   = blockIdx.y * 128;
    const int bn   = blockIdx.x * 128;

    const __nv_bfloat16* srcs[4] = {
        Ah_g + (size_t)bm * K, Al_g + (size_t)bm * K,
        Bh_g + (size_t)bn * K, Bl_g + (size_t)bn * K };

    float acc[4][4][4];
#pragma unroll
    for (int i = 0; i < 4; i++)
#pragma unroll
        for (int j = 0; j < 4; j++)
#pragma unroll
            for (int q = 0; q < 4; q++) acc[i][j][q] = 0.f;

    // fragment addresses (elems within stage arrays)
    const int aBase = (wm * 64 + (lane & 15)) * LDS_ + ((lane >> 4) << 3);
    const int bN    = ((lane >> 4) << 3) + (lane & 7);
    const int bK    = ((lane >> 3) & 1) << 3;
    const int bBase = (wn * 32 + bN) * LDS_ + bK;

    const int NC = K / 32;

    // issue cp.async for chunk k0 into stage st
    auto issue = [&](int k0, int st) {
        uint32_t base = usm + (uint32_t)(st * GSTG * 2);
#pragma unroll
        for (int j = 0; j < 8; j++) {
            int s = tid + (j << 8);
            int arr = s >> 9, r = (s >> 2) & 127, c = s & 3;
            cp16(base + (uint32_t)((arr * 5120 + r * LDS_ + c * 8) * 2),
                 srcs[arr] + (size_t)r * K + k0 + c * 8);
        }
    };

    issue(0, 0);
    CP_COMMIT();

    for (int cIt = 0; cIt < NC; cIt++) {
        const int st = cIt & 1;
        if (cIt + 1 < NC) {
            issue((cIt + 1) * 32, st ^ 1);
            CP_COMMIT();
            CP_WAIT1();
        } else {
            CP_WAIT0();
        }
        __syncthreads();

        const uint32_t sb  = usm + (uint32_t)(st * GSTG * 2);
        const uint32_t uAh = sb, uAl = sb + 5120 * 2;
        const uint32_t uBh = sb + 10240 * 2, uBl = sb + 15360 * 2;

#pragma unroll
        for (int kk = 0; kk < 2; kk++) {
            const int ke = kk << 4;
            uint32_t bh[4][2], bl[4][2];
#pragma unroll
            for (int g = 0; g < 2; g++) {
                uint32_t addr = (uint32_t)((bBase + g * 16 * LDS_ + ke) * 2);
                ldmatrix_x4(bh[g*2][0], bh[g*2][1], bh[g*2+1][0], bh[g*2+1][1],
                            uBh + addr);
                ldmatrix_x4(bl[g*2][0], bl[g*2][1], bl[g*2+1][0], bl[g*2+1][1],
                            uBl + addr);
            }
#pragma unroll
            for (int mi = 0; mi < 4; mi++) {
                uint32_t ah[4], al[4];
                uint32_t addr = (uint32_t)((aBase + mi * 16 * LDS_ + ke) * 2);
                ldmatrix_x4(ah[0], ah[1], ah[2], ah[3], uAh + addr);
                ldmatrix_x4(al[0], al[1], al[2], al[3], uAl + addr);
#pragma unroll
                for (int ni = 0; ni < 4; ni++) {
                    mma_bf16(acc[mi][ni], ah, bh[ni]);
                    mma_bf16(acc[mi][ni], ah, bl[ni]);
                    mma_bf16(acc[mi][ni], al, bh[ni]);
                }
            }
        }
        __syncthreads();
    }

    const int erow = lane >> 2;
    const int ecol = (lane & 3) << 1;
#pragma unroll
    for (int mi = 0; mi < 4; mi++) {
#pragma unroll
        for (int ni = 0; ni < 4; ni++) {
            int r0 = bm + wm * 64 + mi * 16 + erow;
            int cc = bn + wn * 32 + ni * 8 + ecol;
            if (SPLIT) {
                uint32_t h0, l0, h1, l1;
                split2(acc[mi][ni][0], acc[mi][ni][1], h0, l0);
                split2(acc[mi][ni][2], acc[mi][ni][3], h1, l1);
                size_t i0 = ((size_t)r0 * N + cc) >> 1;
                size_t i1 = ((size_t)(r0 + 8) * N + cc) >> 1;
                ((uint32_t*)Ch)[i0] = h0; ((uint32_t*)Cl)[i0] = l0;
                ((uint32_t*)Ch)[i1] = h1; ((uint32_t*)Cl)[i1] = l1;
            } else {
                *(float2*)&C[(size_t)r0 * N + cc] =
                    make_float2(acc[mi][ni][0], acc[mi][ni][1]);
                *(float2*)&C[(size_t)(r0 + 8) * N + cc] =
                    make_float2(acc[mi][ni][2], acc[mi][ni][3]);
            }
        }
    }
}

// ================= Flash attention, pre-split inputs, cp.async KV =========
#define LDQ 72
// smem elems: Qh 9216 | Ql 9216 | 2 KV stages x (Kh,Kl,Vh,Vl 4608 each)
#define AKV   18432
#define ATT_SMEM ((18432 + 2 * AKV) * 2)   // 110592 bytes

__global__ __launch_bounds__(256, 1)
void attn_ps(const __nv_bfloat16* __restrict__ Qh_g, const __nv_bfloat16* __restrict__ Ql_g,
             const __nv_bfloat16* __restrict__ Kh_g, const __nv_bfloat16* __restrict__ Kl_g,
             const __nv_bfloat16* __restrict__ Vh_g, const __nv_bfloat16* __restrict__ Vl_g,
             __nv_bfloat16* __restrict__ Oh, __nv_bfloat16* __restrict__ Ol)
{
    extern __shared__ __nv_bfloat16 sm[];
    const uint32_t usm = smem_u32(sm);

    const int b = blockIdx.z, h = blockIdx.y, qt = blockIdx.x;
    const int tid = threadIdx.x, lane = tid & 31, w = tid >> 5;
    const int kvh = h >> 2;
    const int qBase = qt * 128;
    const int wq0 = qBase + 16 * w;

    const __nv_bfloat16* kvsrc[4] = {
        Kh_g + (size_t)(b * SEQ) * KVD + kvh * HD,
        Kl_g + (size_t)(b * SEQ) * KVD + kvh * HD,
        Vh_g + (size_t)(b * SEQ) * KVD + kvh * HD,
        Vl_g + (size_t)(b * SEQ) * KVD + kvh * HD };

    // --- issue Q (group) ---
    {
        const __nv_bfloat16* qs[2] = {
            Qh_g + (size_t)(b * SEQ + qBase) * DIM + h * HD,
            Ql_g + (size_t)(b * SEQ + qBase) * DIM + h * HD };
#pragma unroll
        for (int j = 0; j < 8; j++) {
            int s = tid + (j << 8);
            int arr = s >> 10, r = (s >> 3) & 127, c = s & 7;
            cp16(usm + (uint32_t)((arr * 9216 + r * LDQ + c * 8) * 2),
                 qs[arr] + (size_t)r * DIM + c * 8);
        }
        CP_COMMIT();
    }

    auto issue_kv = [&](int j, int st) {
        int kvBase = j * 64;
        uint32_t base = usm + (uint32_t)((18432 + st * AKV) * 2);
#pragma unroll
        for (int q = 0; q < 8; q++) {
            int s = tid + (q << 8);
            int arr = s >> 9, r = (s >> 3) & 63, c = s & 7;
            cp16(base + (uint32_t)((arr * 4608 + r * LDQ + c * 8) * 2),
                 kvsrc[arr] + (size_t)(kvBase + r) * KVD + c * 8);
        }
    };

    const int ntiles = 2 * qt + 2;
    issue_kv(0, 0);
    CP_COMMIT();

    // wait for Q (kv0 may still be pending)
    CP_WAIT1();
    __syncthreads();

    // Q fragments resident in registers
    uint32_t qh[4][4], ql[4][4];
    {
        int off0 = (16*w + (lane & 15)) * LDQ + ((lane >> 4) << 3);
#pragma unroll
        for (int kb = 0; kb < 4; kb++) {
            uint32_t off = (uint32_t)((off0 + kb * 16) * 2);
            ldmatrix_x4(qh[kb][0], qh[kb][1], qh[kb][2], qh[kb][3], usm + off);
            ldmatrix_x4(ql[kb][0], ql[kb][1], ql[kb][2], ql[kb][3],
                        usm + (uint32_t)(9216 * 2) + off);
        }
    }

    float o[8][4];
#pragma unroll
    for (int nb = 0; nb < 8; nb++)
#pragma unroll
        for (int q = 0; q < 4; q++) o[nb][q] = 0.f;
    float m0 = -3e38f, m1 = -3e38f, l0 = 0.f, l1 = 0.f;

    const int bN = ((lane >> 4) << 3) + (lane & 7);
    const int bK = ((lane >> 3) & 1) << 3;
    const int vRow = lane & 15, vCol = (lane >> 4) << 3;
    const int r0   = lane >> 2;
    const int c2   = (lane & 3) << 1;
    const int qi0  = wq0 + r0, qi1 = qi0 + 8;

    for (int j = 0; j < ntiles; j++) {
        const int kvBase = j * 64;
        const int st = j & 1;
        if (j + 1 < ntiles) {
            issue_kv(j + 1, st ^ 1);
            CP_COMMIT();
            CP_WAIT1();
        } else {
            CP_WAIT0();
        }
        __syncthreads();

        if (kvBase <= wq0 + 15) {
            const uint32_t kvb = usm + (uint32_t)((18432 + st * AKV) * 2);
            const uint32_t uKh = kvb, uKl = kvb + 4608 * 2;
            const uint32_t uVh = kvb + 9216 * 2, uVl = kvb + 13824 * 2;

            // ---- S = Q K^T ----
            float sa[8][4];
#pragma unroll
            for (int nb = 0; nb < 8; nb++)
#pragma unroll
                for (int q = 0; q < 4; q++) sa[nb][q] = 0.f;

#pragma unroll
            for (int kb = 0; kb < 4; kb++) {
#pragma unroll
                for (int g = 0; g < 4; g++) {
                    uint32_t off = (uint32_t)(((g*16 + bN) * LDQ + kb*16 + bK) * 2);
                    uint32_t b0[2], b1[2], c0[2], c1[2];
                    ldmatrix_x4(b0[0], b0[1], b1[0], b1[1], uKh + off);
                    ldmatrix_x4(c0[0], c0[1], c1[0], c1[1], uKl + off);
                    mma_bf16(sa[2*g],   qh[kb], b0);
                    mma_bf16(sa[2*g],   qh[kb], c0);
                    mma_bf16(sa[2*g],   ql[kb], b0);
                    mma_bf16(sa[2*g+1], qh[kb], b1);
                    mma_bf16(sa[2*g+1], qh[kb], c1);
                    mma_bf16(sa[2*g+1], ql[kb], b1);
                }
            }

            // ---- causal mask ----
            if (kvBase + 63 > wq0) {
#pragma unroll
                for (int nb = 0; nb < 8; nb++) {
                    int col = kvBase + nb * 8 + c2;
                    if (col     > qi0) sa[nb][0] = -3e38f;
                    if (col + 1 > qi0) sa[nb][1] = -3e38f;
                    if (col     > qi1) sa[nb][2] = -3e38f;
                    if (col + 1 > qi1) sa[nb][3] = -3e38f;
                }
            }

            // ---- online softmax ----
            float mx0 = -3e38f, mx1 = -3e38f;
#pragma unroll
            for (int nb = 0; nb < 8; nb++) {
                mx0 = fmaxf(mx0, fmaxf(sa[nb][0], sa[nb][1]));
                mx1 = fmaxf(mx1, fmaxf(sa[nb][2], sa[nb][3]));
            }
            mx0 = fmaxf(mx0, __shfl_xor_sync(0xffffffffu, mx0, 1));
            mx0 = fmaxf(mx0, __shfl_xor_sync(0xffffffffu, mx0, 2));
            mx1 = fmaxf(mx1, __shfl_xor_sync(0xffffffffu, mx1, 1));
            mx1 = fmaxf(mx1, __shfl_xor_sync(0xffffffffu, mx1, 2));
            float mn0 = fmaxf(m0, mx0), mn1 = fmaxf(m1, mx1);
            float a0 = fexp2c(m0 - mn0), a1 = fexp2c(m1 - mn1);
            m0 = mn0; m1 = mn1;

            float s0 = 0.f, s1 = 0.f;
#pragma unroll
            for (int nb = 0; nb < 8; nb++) {
                sa[nb][0] = fexp2c(sa[nb][0] - mn0); s0 += sa[nb][0];
                sa[nb][1] = fexp2c(sa[nb][1] - mn0); s0 += sa[nb][1];
                sa[nb][2] = fexp2c(sa[nb][2] - mn1); s1 += sa[nb][2];
                sa[nb][3] = fexp2c(sa[nb][3] - mn1); s1 += sa[nb][3];
            }
            s0 += __shfl_xor_sync(0xffffffffu, s0, 1);
            s0 += __shfl_xor_sync(0xffffffffu, s0, 2);
            s1 += __shfl_xor_sync(0xffffffffu, s1, 1);
            s1 += __shfl_xor_sync(0xffffffffu, s1, 2);
            l0 = l0 * a0 + s0;
            l1 = l1 * a1 + s1;
#pragma unroll
            for (int nb = 0; nb < 8; nb++) {
                o[nb][0] *= a0; o[nb][1] *= a0;
                o[nb][2] *= a1; o[nb][3] *= a1;
            }

            // ---- O += P V ----
#pragma unroll
            for (int jk = 0; jk < 4; jk++) {
                uint32_t ph[4], pl[4];
                split2(sa[2*jk][0],   sa[2*jk][1],   ph[0], pl[0]);
                split2(sa[2*jk][2],   sa[2*jk][3],   ph[1], pl[1]);
                split2(sa[2*jk+1][0], sa[2*jk+1][1], ph[2], pl[2]);
                split2(sa[2*jk+1][2], sa[2*jk+1][3], ph[3], pl[3]);
#pragma unroll
                for (int g = 0; g < 4; g++) {
                    uint32_t off = (uint32_t)(((jk*16 + vRow) * LDQ + g*16 + vCol) * 2);
                    uint32_t vh0[2], vh1[2], vl0[2], vl1[2];
                    ldmatrix_x4_trans(vh0[0], vh0[1], vh1[0], vh1[1], uVh + off);
                    ldmatrix_x4_trans(vl0[0], vl0[1], vl1[0], vl1[1], uVl + off);
                    mma_bf16(o[2*g],   ph, vh0);
                    mma_bf16(o[2*g],   ph, vl0);
                    mma_bf16(o[2*g],   pl, vh0);
                    mma_bf16(o[2*g+1], ph, vh1);
                    mma_bf16(o[2*g+1], ph, vl1);
                    mma_bf16(o[2*g+1], pl, vh1);
                }
            }
        }
        __syncthreads();
    }

    // ---- epilogue: normalize + split-write ----
    float i0 = __fdividef(1.f, l0), i1 = __fdividef(1.f, l1);
#pragma unroll
    for (int nb = 0; nb < 8; nb++) {
        size_t e0 = ((size_t)(b*SEQ + qi0) * DIM + h*HD + nb*8 + c2) >> 1;
        size_t e1 = ((size_t)(b*SEQ + qi1) * DIM + h*HD + nb*8 + c2) >> 1;
        uint32_t h0, lo0, h1, lo1;
        split2(o[nb][0] * i0, o[nb][1] * i0, h0, lo0);
        split2(o[nb][2] * i1, o[nb][3] * i1, h1, lo1);
        ((uint32_t*)Oh)[e0] = h0; ((uint32_t*)Ol)[e0] = lo0;
        ((uint32_t*)Oh)[e1] = h1; ((uint32_t*)Ol)[e1] = lo1;
    }
}

// =============================== Launch ====================================
extern "C" void kernel_launch(void* const* d_in, const int* in_sizes, int n_in,
                              void* d_out, int out_size)
{
    const float* x  = (const float*)d_in[0];
    const float* wq = (const float*)d_in[1];
    const float* wk = (const float*)d_in[2];
    const float* wv = (const float*)d_in[3];
    const float* wo = (const float*)d_in[4];
    float* out = (float*)d_out;

    __nv_bfloat16 *xh, *xl, *wqh, *wql, *wkh, *wkl, *wvh, *wvl, *woh, *wol;
    __nv_bfloat16 *Qh, *Ql, *Kh, *Kl, *Vh, *Vl, *Oh, *Ol;
    cudaGetSymbolAddress((void**)&xh,  g_xh);  cudaGetSymbolAddress((void**)&xl,  g_xl);
    cudaGetSymbolAddress((void**)&wqh, g_wqh); cudaGetSymbolAddress((void**)&wql, g_wql);
    cudaGetSymbolAddress((void**)&wkh, g_wkh); cudaGetSymbolAddress((void**)&wkl, g_wkl);
    cudaGetSymbolAddress((void**)&wvh, g_wvh); cudaGetSymbolAddress((void**)&wvl, g_wvl);
    cudaGetSymbolAddress((void**)&woh, g_woh); cudaGetSymbolAddress((void**)&wol, g_wol);
    cudaGetSymbolAddress((void**)&Qh,  g_Qh);  cudaGetSymbolAddress((void**)&Ql,  g_Ql);
    cudaGetSymbolAddress((void**)&Kh,  g_Kh);  cudaGetSymbolAddress((void**)&Kl,  g_Kl);
    cudaGetSymbolAddress((void**)&Vh,  g_Vh);  cudaGetSymbolAddress((void**)&Vl,  g_Vl);
    cudaGetSymbolAddress((void**)&Oh,  g_Oh);  cudaGetSymbolAddress((void**)&Ol,  g_Ol);

    cudaFuncSetAttribute(gemm_ps<0>, cudaFuncAttributeMaxDynamicSharedMemorySize, GEMM_SMEM);
    cudaFuncSetAttribute(gemm_ps<1>, cudaFuncAttributeMaxDynamicSharedMemorySize, GEMM_SMEM);
    cudaFuncSetAttribute(attn_ps, cudaFuncAttributeMaxDynamicSharedMemorySize, ATT_SMEM);

    dim3 blk(256);
    // one-time input splits
    split_f32<<<(MTOT*DIM/4 + 255)/256, blk>>>(x,  xh,  xl,  MTOT*DIM/4);
    split_f32<<<(DIM*DIM/4  + 255)/256, blk>>>(wq, wqh, wql, DIM*DIM/4);
    split_f32<<<(KVD*DIM/4  + 255)/256, blk>>>(wk, wkh, wkl, KVD*DIM/4);
    split_f32<<<(KVD*DIM/4  + 255)/256, blk>>>(wv, wvh, wvl, KVD*DIM/4);
    split_f32<<<(DIM*DIM/4  + 255)/256, blk>>>(wo, woh, wol, DIM*DIM/4);

    gemm_ps<1><<<dim3(DIM/128, MTOT/128), blk, GEMM_SMEM>>>(
        xh, xl, wqh, wql, nullptr, Qh, Ql, MTOT, DIM, DIM);
    gemm_ps<1><<<dim3(KVD/128, MTOT/128), blk, GEMM_SMEM>>>(
        xh, xl, wkh, wkl, nullptr, Kh, Kl, MTOT, KVD, DIM);
    gemm_ps<1><<<dim3(KVD/128, MTOT/128), blk, GEMM_SMEM>>>(
        xh, xl, wvh, wvl, nullptr, Vh, Vl, MTOT, KVD, DIM);
    attn_ps<<<dim3(SEQ/128, NH, BATCH), blk, ATT_SMEM>>>(
        Qh, Ql, Kh, Kl, Vh, Vl, Oh, Ol);
    gemm_ps<0><<<dim3(DIM/128, MTOT/128), blk, GEMM_SMEM>>>(
        Oh, Ol, woh, wol, out, nullptr, nullptr, MTOT, DIM, DIM);
}

// round 6
// speedup vs baseline: 3.2028x; 1.0038x over previous
#include <cuda_runtime.h>
#include <cuda_bf16.h>
#include <cstdint>
#include <math.h>

// Problem constants
#define BATCH 2
#define SEQ   2048
#define DIM   2048
#define NH    32
#define NKV   8
#define HD    64
#define KVD   (NKV*HD)    // 512
#define MTOT  (BATCH*SEQ) // 4096

// Scratch (device globals: allocation-free) — all pre-split bf16 pairs
__device__ __nv_bfloat16 g_xh [MTOT * DIM],  g_xl [MTOT * DIM];
__device__ __nv_bfloat16 g_wqh[DIM * DIM],   g_wql[DIM * DIM];
__device__ __nv_bfloat16 g_wkh[KVD * DIM],   g_wkl[KVD * DIM];
__device__ __nv_bfloat16 g_wvh[KVD * DIM],   g_wvl[KVD * DIM];
__device__ __nv_bfloat16 g_woh[DIM * DIM],   g_wol[DIM * DIM];
__device__ __nv_bfloat16 g_Qh [MTOT * DIM],  g_Ql [MTOT * DIM];
__device__ __nv_bfloat16 g_Kh [MTOT * KVD],  g_Kl [MTOT * KVD];
__device__ __nv_bfloat16 g_Vh [MTOT * KVD],  g_Vl [MTOT * KVD];
__device__ __nv_bfloat16 g_Oh [MTOT * DIM],  g_Ol [MTOT * DIM];

// ============================ helpers ======================================
__device__ __forceinline__ uint32_t smem_u32(const void* p) {
    uint32_t a;
    asm("{ .reg .u64 t; cvta.to.shared.u64 t, %1; cvt.u32.u64 %0, t; }"
        : "=r"(a) : "l"(p));
    return a;
}
__device__ __forceinline__ void cp16(uint32_t dst, const void* src) {
    asm volatile("cp.async.cg.shared.global [%0], [%1], 16;"
                 :: "r"(dst), "l"(src) : "memory");
}
#define CP_COMMIT() asm volatile("cp.async.commit_group;" ::: "memory")
#define CP_WAIT0()  asm volatile("cp.async.wait_group 0;" ::: "memory")
#define CP_WAIT1()  asm volatile("cp.async.wait_group 1;" ::: "memory")

__device__ __forceinline__ void ldmatrix_x4(uint32_t& r0, uint32_t& r1,
                                            uint32_t& r2, uint32_t& r3,
                                            uint32_t addr) {
    asm volatile("ldmatrix.sync.aligned.m8n8.x4.shared.b16 {%0,%1,%2,%3}, [%4];"
                 : "=r"(r0), "=r"(r1), "=r"(r2), "=r"(r3) : "r"(addr));
}
__device__ __forceinline__ void ldmatrix_x4_trans(uint32_t& r0, uint32_t& r1,
                                                  uint32_t& r2, uint32_t& r3,
                                                  uint32_t addr) {
    asm volatile("ldmatrix.sync.aligned.m8n8.x4.trans.shared.b16 {%0,%1,%2,%3}, [%4];"
                 : "=r"(r0), "=r"(r1), "=r"(r2), "=r"(r3) : "r"(addr));
}
__device__ __forceinline__ void mma_bf16(float* d, const uint32_t* a,
                                         const uint32_t* b) {
    asm volatile(
        "mma.sync.aligned.m16n8k16.row.col.f32.bf16.bf16.f32 "
        "{%0,%1,%2,%3}, {%4,%5,%6,%7}, {%8,%9}, {%0,%1,%2,%3};"
        : "+f"(d[0]), "+f"(d[1]), "+f"(d[2]), "+f"(d[3])
        : "r"(a[0]), "r"(a[1]), "r"(a[2]), "r"(a[3]), "r"(b[0]), "r"(b[1]));
}

// fp32 pair -> packed (hi,lo) bf16x2
__device__ __forceinline__ void split2(float a, float b, uint32_t& hi, uint32_t& lo) {
    __nv_bfloat16 ha = __float2bfloat16(a), hb = __float2bfloat16(b);
    hi = (uint32_t)__bfloat16_as_ushort(ha) |
         ((uint32_t)__bfloat16_as_ushort(hb) << 16);
    float ra = a - __bfloat162float(ha);
    float rb = b - __bfloat162float(hb);
    uint32_t d;
    asm("cvt.rn.bf16x2.f32 %0, %1, %2;" : "=r"(d) : "f"(rb), "f"(ra));
    lo = d;
}

// exp(x*0.125) via 2^y polynomial on FMA pipe (x <= 0)
__device__ __forceinline__ float fexp2c(float x) {
    float y = fmaxf(x * 0.1803368801f, -126.f);
    float r = rintf(y);
    float f = y - r;
    float p = 1.3333558e-3f;
    p = fmaf(p, f, 9.6181291e-3f);
    p = fmaf(p, f, 5.5504109e-2f);
    p = fmaf(p, f, 2.4022651e-1f);
    p = fmaf(p, f, 6.9314718e-1f);
    p = fmaf(p, f, 1.0f);
    return p * __int_as_float(((int)r + 127) << 23);
}

// ====================== pre-split kernel (fp32 -> hi/lo bf16) ==============
__global__ __launch_bounds__(256)
void split_f32(const float* __restrict__ in, __nv_bfloat16* __restrict__ hi,
               __nv_bfloat16* __restrict__ lo, int n4)
{
    int i = blockIdx.x * 256 + threadIdx.x;
    if (i >= n4) return;
    float4 v = ((const float4*)in)[i];
    uint32_t h0, l0, h1, l1;
    split2(v.x, v.y, h0, l0);
    split2(v.z, v.w, h1, l1);
    ((uint2*)hi)[i] = make_uint2(h0, h1);
    ((uint2*)lo)[i] = make_uint2(l0, l1);
}

// ===================== pre-split bf16 GEMM body ============================
// C[128,128] tile of A[M,K] @ B[N,K]^T; pointers pre-offset to tile origin.
#define LDS_ 40
#define GSTG 20480
#define GEMM_SMEM (2 * GSTG * 2)   // 81920 bytes

template<int SPLIT>
__device__ __forceinline__ void gemm_body(
    const __nv_bfloat16* __restrict__ Ah_t, const __nv_bfloat16* __restrict__ Al_t,
    const __nv_bfloat16* __restrict__ Bh_t, const __nv_bfloat16* __restrict__ Bl_t,
    float* __restrict__ C, __nv_bfloat16* __restrict__ Ch,
    __nv_bfloat16* __restrict__ Cl, int ldc, int K, __nv_bfloat16* gsm)
{
    const uint32_t usm = smem_u32(gsm);
    const int tid  = threadIdx.x;
    const int lane = tid & 31;
    const int wid  = tid >> 5;
    const int wm   = wid & 1;
    const int wn   = wid >> 1;

    const __nv_bfloat16* srcs[4] = { Ah_t, Al_t, Bh_t, Bl_t };

    float acc[4][4][4];
#pragma unroll
    for (int i = 0; i < 4; i++)
#pragma unroll
        for (int j = 0; j < 4; j++)
#pragma unroll
            for (int q = 0; q < 4; q++) acc[i][j][q] = 0.f;

    const int aBase = (wm * 64 + (lane & 15)) * LDS_ + ((lane >> 4) << 3);
    const int bN    = ((lane >> 4) << 3) + (lane & 7);
    const int bK    = ((lane >> 3) & 1) << 3;
    const int bBase = (wn * 32 + bN) * LDS_ + bK;

    const int NC = K / 32;

    auto issue = [&](int k0, int st) {
        uint32_t base = usm + (uint32_t)(st * GSTG * 2);
#pragma unroll
        for (int j = 0; j < 8; j++) {
            int s = tid + (j << 8);
            int arr = s >> 9, r = (s >> 2) & 127, c = s & 3;
            cp16(base + (uint32_t)((arr * 5120 + r * LDS_ + c * 8) * 2),
                 srcs[arr] + (size_t)r * K + k0 + c * 8);
        }
    };

    issue(0, 0);
    CP_COMMIT();

    for (int cIt = 0; cIt < NC; cIt++) {
        const int st = cIt & 1;
        if (cIt + 1 < NC) {
            issue((cIt + 1) * 32, st ^ 1);
            CP_COMMIT();
            CP_WAIT1();
        } else {
            CP_WAIT0();
        }
        __syncthreads();

        const uint32_t sb  = usm + (uint32_t)(st * GSTG * 2);
        const uint32_t uAh = sb, uAl = sb + 5120 * 2;
        const uint32_t uBh = sb + 10240 * 2, uBl = sb + 15360 * 2;

#pragma unroll
        for (int kk = 0; kk < 2; kk++) {
            const int ke = kk << 4;
            uint32_t bh[4][2], bl[4][2];
#pragma unroll
            for (int g = 0; g < 2; g++) {
                uint32_t addr = (uint32_t)((bBase + g * 16 * LDS_ + ke) * 2);
                ldmatrix_x4(bh[g*2][0], bh[g*2][1], bh[g*2+1][0], bh[g*2+1][1],
                            uBh + addr);
                ldmatrix_x4(bl[g*2][0], bl[g*2][1], bl[g*2+1][0], bl[g*2+1][1],
                            uBl + addr);
            }
#pragma unroll
            for (int mi = 0; mi < 4; mi++) {
                uint32_t ah[4], al[4];
                uint32_t addr = (uint32_t)((aBase + mi * 16 * LDS_ + ke) * 2);
                ldmatrix_x4(ah[0], ah[1], ah[2], ah[3], uAh + addr);
                ldmatrix_x4(al[0], al[1], al[2], al[3], uAl + addr);
                // term-outer ordering: dependent MMAs separated by 4
#pragma unroll
                for (int ni = 0; ni < 4; ni++) mma_bf16(acc[mi][ni], ah, bh[ni]);
#pragma unroll
                for (int ni = 0; ni < 4; ni++) mma_bf16(acc[mi][ni], ah, bl[ni]);
#pragma unroll
                for (int ni = 0; ni < 4; ni++) mma_bf16(acc[mi][ni], al, bh[ni]);
            }
        }
        __syncthreads();
    }

    const int erow = lane >> 2;
    const int ecol = (lane & 3) << 1;
#pragma unroll
    for (int mi = 0; mi < 4; mi++) {
#pragma unroll
        for (int ni = 0; ni < 4; ni++) {
            int r0 = wm * 64 + mi * 16 + erow;
            int cc = wn * 32 + ni * 8 + ecol;
            if (SPLIT) {
                uint32_t h0, l0, h1, l1;
                split2(acc[mi][ni][0], acc[mi][ni][1], h0, l0);
                split2(acc[mi][ni][2], acc[mi][ni][3], h1, l1);
                size_t i0 = ((size_t)r0 * ldc + cc) >> 1;
                size_t i1 = ((size_t)(r0 + 8) * ldc + cc) >> 1;
                ((uint32_t*)Ch)[i0] = h0; ((uint32_t*)Cl)[i0] = l0;
                ((uint32_t*)Ch)[i1] = h1; ((uint32_t*)Cl)[i1] = l1;
            } else {
                *(float2*)&C[(size_t)r0 * ldc + cc] =
                    make_float2(acc[mi][ni][0], acc[mi][ni][1]);
                *(float2*)&C[(size_t)(r0 + 8) * ldc + cc] =
                    make_float2(acc[mi][ni][2], acc[mi][ni][3]);
            }
        }
    }
}

// Fused Q/K/V projection: grid.x = 24 n-tiles (16 Q | 4 K | 4 V), grid.y = 32
__global__ __launch_bounds__(256, 2)
void gemm_qkv(const __nv_bfloat16* __restrict__ xh, const __nv_bfloat16* __restrict__ xl,
              const __nv_bfloat16* __restrict__ wqh, const __nv_bfloat16* __restrict__ wql,
              const __nv_bfloat16* __restrict__ wkh, const __nv_bfloat16* __restrict__ wkl,
              const __nv_bfloat16* __restrict__ wvh, const __nv_bfloat16* __restrict__ wvl,
              __nv_bfloat16* __restrict__ Qh, __nv_bfloat16* __restrict__ Ql,
              __nv_bfloat16* __restrict__ Kh, __nv_bfloat16* __restrict__ Kl,
              __nv_bfloat16* __restrict__ Vh, __nv_bfloat16* __restrict__ Vl)
{
    extern __shared__ __nv_bfloat16 gsm[];
    const int nt = blockIdx.x;
    const int bm = blockIdx.y * 128;
    const __nv_bfloat16 *Bh, *Bl;
    __nv_bfloat16 *Ch, *Cl;
    int ldc, bn;
    if (nt < 16)      { Bh = wqh; Bl = wql; Ch = Qh; Cl = Ql; ldc = DIM; bn = nt * 128; }
    else if (nt < 20) { Bh = wkh; Bl = wkl; Ch = Kh; Cl = Kl; ldc = KVD; bn = (nt - 16) * 128; }
    else              { Bh = wvh; Bl = wvl; Ch = Vh; Cl = Vl; ldc = KVD; bn = (nt - 20) * 128; }
    gemm_body<1>(xh + (size_t)bm * DIM, xl + (size_t)bm * DIM,
                 Bh + (size_t)bn * DIM, Bl + (size_t)bn * DIM,
                 nullptr,
                 Ch + (size_t)bm * ldc + bn, Cl + (size_t)bm * ldc + bn,
                 ldc, DIM, gsm);
}

// Output projection: fp32 out
__global__ __launch_bounds__(256, 2)
void gemm_o(const __nv_bfloat16* __restrict__ Ah, const __nv_bfloat16* __restrict__ Al,
            const __nv_bfloat16* __restrict__ Bh, const __nv_bfloat16* __restrict__ Bl,
            float* __restrict__ C)
{
    extern __shared__ __nv_bfloat16 gsm[];
    const int bm = blockIdx.y * 128, bn = blockIdx.x * 128;
    gemm_body<0>(Ah + (size_t)bm * DIM, Al + (size_t)bm * DIM,
                 Bh + (size_t)bn * DIM, Bl + (size_t)bn * DIM,
                 C + (size_t)bm * DIM + bn, nullptr, nullptr,
                 DIM, DIM, gsm);
}

// ================= Flash attention, pre-split inputs, cp.async KV =========
#define LDQ 72
#define AKV   18432
#define ATT_SMEM ((18432 + 2 * AKV) * 2)   // 110592 bytes

__global__ __launch_bounds__(256, 1)
void attn_ps(const __nv_bfloat16* __restrict__ Qh_g, const __nv_bfloat16* __restrict__ Ql_g,
             const __nv_bfloat16* __restrict__ Kh_g, const __nv_bfloat16* __restrict__ Kl_g,
             const __nv_bfloat16* __restrict__ Vh_g, const __nv_bfloat16* __restrict__ Vl_g,
             __nv_bfloat16* __restrict__ Oh, __nv_bfloat16* __restrict__ Ol)
{
    extern __shared__ __nv_bfloat16 sm[];
    const uint32_t usm = smem_u32(sm);

    const int b = blockIdx.z, h = blockIdx.y;
    const int qt = (int)gridDim.x - 1 - (int)blockIdx.x;   // heavy tiles first
    const int tid = threadIdx.x, lane = tid & 31, w = tid >> 5;
    const int kvh = h >> 2;
    const int qBase = qt * 128;
    const int wq0 = qBase + 16 * w;

    const __nv_bfloat16* kvsrc[4] = {
        Kh_g + (size_t)(b * SEQ) * KVD + kvh * HD,
        Kl_g + (size_t)(b * SEQ) * KVD + kvh * HD,
        Vh_g + (size_t)(b * SEQ) * KVD + kvh * HD,
        Vl_g + (size_t)(b * SEQ) * KVD + kvh * HD };

    // --- issue Q ---
    {
        const __nv_bfloat16* qs[2] = {
            Qh_g + (size_t)(b * SEQ + qBase) * DIM + h * HD,
            Ql_g + (size_t)(b * SEQ + qBase) * DIM + h * HD };
#pragma unroll
        for (int j = 0; j < 8; j++) {
            int s = tid + (j << 8);
            int arr = s >> 10, r = (s >> 3) & 127, c = s & 7;
            cp16(usm + (uint32_t)((arr * 9216 + r * LDQ + c * 8) * 2),
                 qs[arr] + (size_t)r * DIM + c * 8);
        }
        CP_COMMIT();
    }

    auto issue_kv = [&](int j, int st) {
        int kvBase = j * 64;
        uint32_t base = usm + (uint32_t)((18432 + st * AKV) * 2);
#pragma unroll
        for (int q = 0; q < 8; q++) {
            int s = tid + (q << 8);
            int arr = s >> 9, r = (s >> 3) & 63, c = s & 7;
            cp16(base + (uint32_t)((arr * 4608 + r * LDQ + c * 8) * 2),
                 kvsrc[arr] + (size_t)(kvBase + r) * KVD + c * 8);
        }
    };

    const int ntiles = 2 * qt + 2;
    issue_kv(0, 0);
    CP_COMMIT();

    CP_WAIT1();
    __syncthreads();

    uint32_t qh[4][4], ql[4][4];
    {
        int off0 = (16*w + (lane & 15)) * LDQ + ((lane >> 4) << 3);
#pragma unroll
        for (int kb = 0; kb < 4; kb++) {
            uint32_t off = (uint32_t)((off0 + kb * 16) * 2);
            ldmatrix_x4(qh[kb][0], qh[kb][1], qh[kb][2], qh[kb][3], usm + off);
            ldmatrix_x4(ql[kb][0], ql[kb][1], ql[kb][2], ql[kb][3],
                        usm + (uint32_t)(9216 * 2) + off);
        }
    }

    float o[8][4];
#pragma unroll
    for (int nb = 0; nb < 8; nb++)
#pragma unroll
        for (int q = 0; q < 4; q++) o[nb][q] = 0.f;
    float m0 = -3e38f, m1 = -3e38f, l0 = 0.f, l1 = 0.f;

    const int bN = ((lane >> 4) << 3) + (lane & 7);
    const int bK = ((lane >> 3) & 1) << 3;
    const int vRow = lane & 15, vCol = (lane >> 4) << 3;
    const int r0   = lane >> 2;
    const int c2   = (lane & 3) << 1;
    const int qi0  = wq0 + r0, qi1 = qi0 + 8;

    for (int j = 0; j < ntiles; j++) {
        const int kvBase = j * 64;
        const int st = j & 1;
        if (j + 1 < ntiles) {
            issue_kv(j + 1, st ^ 1);
            CP_COMMIT();
            CP_WAIT1();
        } else {
            CP_WAIT0();
        }
        __syncthreads();

        if (kvBase <= wq0 + 15) {
            const uint32_t kvb = usm + (uint32_t)((18432 + st * AKV) * 2);
            const uint32_t uKh = kvb, uKl = kvb + 4608 * 2;
            const uint32_t uVh = kvb + 9216 * 2, uVl = kvb + 13824 * 2;

            // ---- S = Q K^T (term-outer: 8 independent MMAs between deps) ----
            float sa[8][4];
#pragma unroll
            for (int nb = 0; nb < 8; nb++)
#pragma unroll
                for (int q = 0; q < 4; q++) sa[nb][q] = 0.f;

#pragma unroll
            for (int kb = 0; kb < 4; kb++) {
                uint32_t bhf[8][2], blf[8][2];
#pragma unroll
                for (int g = 0; g < 4; g++) {
                    uint32_t off = (uint32_t)(((g*16 + bN) * LDQ + kb*16 + bK) * 2);
                    ldmatrix_x4(bhf[2*g][0], bhf[2*g][1], bhf[2*g+1][0], bhf[2*g+1][1],
                                uKh + off);
                    ldmatrix_x4(blf[2*g][0], blf[2*g][1], blf[2*g+1][0], blf[2*g+1][1],
                                uKl + off);
                }
#pragma unroll
                for (int nb = 0; nb < 8; nb++) mma_bf16(sa[nb], qh[kb], bhf[nb]);
#pragma unroll
                for (int nb = 0; nb < 8; nb++) mma_bf16(sa[nb], qh[kb], blf[nb]);
#pragma unroll
                for (int nb = 0; nb < 8; nb++) mma_bf16(sa[nb], ql[kb], bhf[nb]);
            }

            // ---- causal mask ----
            if (kvBase + 63 > wq0) {
#pragma unroll
                for (int nb = 0; nb < 8; nb++) {
                    int col = kvBase + nb * 8 + c2;
                    if (col     > qi0) sa[nb][0] = -3e38f;
                    if (col + 1 > qi0) sa[nb][1] = -3e38f;
                    if (col     > qi1) sa[nb][2] = -3e38f;
                    if (col + 1 > qi1) sa[nb][3] = -3e38f;
                }
            }

            // ---- online softmax ----
            float mx0 = -3e38f, mx1 = -3e38f;
#pragma unroll
            for (int nb = 0; nb < 8; nb++) {
                mx0 = fmaxf(mx0, fmaxf(sa[nb][0], sa[nb][1]));
                mx1 = fmaxf(mx1, fmaxf(sa[nb][2], sa[nb][3]));
            }
            mx0 = fmaxf(mx0, __shfl_xor_sync(0xffffffffu, mx0, 1));
            mx0 = fmaxf(mx0, __shfl_xor_sync(0xffffffffu, mx0, 2));
            mx1 = fmaxf(mx1, __shfl_xor_sync(0xffffffffu, mx1, 1));
            mx1 = fmaxf(mx1, __shfl_xor_sync(0xffffffffu, mx1, 2));
            float mn0 = fmaxf(m0, mx0), mn1 = fmaxf(m1, mx1);
            float a0 = fexp2c(m0 - mn0), a1 = fexp2c(m1 - mn1);
            m0 = mn0; m1 = mn1;

            float s0 = 0.f, s1 = 0.f;
#pragma unroll
            for (int nb = 0; nb < 8; nb++) {
                sa[nb][0] = fexp2c(sa[nb][0] - mn0); s0 += sa[nb][0];
                sa[nb][1] = fexp2c(sa[nb][1] - mn0); s0 += sa[nb][1];
                sa[nb][2] = fexp2c(sa[nb][2] - mn1); s1 += sa[nb][2];
                sa[nb][3] = fexp2c(sa[nb][3] - mn1); s1 += sa[nb][3];
            }
            s0 += __shfl_xor_sync(0xffffffffu, s0, 1);
            s0 += __shfl_xor_sync(0xffffffffu, s0, 2);
            s1 += __shfl_xor_sync(0xffffffffu, s1, 1);
            s1 += __shfl_xor_sync(0xffffffffu, s1, 2);
            l0 = l0 * a0 + s0;
            l1 = l1 * a1 + s1;
#pragma unroll
            for (int nb = 0; nb < 8; nb++) {
                o[nb][0] *= a0; o[nb][1] *= a0;
                o[nb][2] *= a1; o[nb][3] *= a1;
            }

            // ---- O += P V (term-outer: 8 independent MMAs between deps) ----
#pragma unroll
            for (int jk = 0; jk < 4; jk++) {
                uint32_t ph[4], pl[4];
                split2(sa[2*jk][0],   sa[2*jk][1],   ph[0], pl[0]);
                split2(sa[2*jk][2],   sa[2*jk][3],   ph[1], pl[1]);
                split2(sa[2*jk+1][0], sa[2*jk+1][1], ph[2], pl[2]);
                split2(sa[2*jk+1][2], sa[2*jk+1][3], ph[3], pl[3]);
                uint32_t vhf[8][2], vlf[8][2];
#pragma unroll
                for (int g = 0; g < 4; g++) {
                    uint32_t off = (uint32_t)(((jk*16 + vRow) * LDQ + g*16 + vCol) * 2);
                    ldmatrix_x4_trans(vhf[2*g][0], vhf[2*g][1], vhf[2*g+1][0], vhf[2*g+1][1],
                                      uVh + off);
                    ldmatrix_x4_trans(vlf[2*g][0], vlf[2*g][1], vlf[2*g+1][0], vlf[2*g+1][1],
                                      uVl + off);
                }
#pragma unroll
                for (int nb = 0; nb < 8; nb++) mma_bf16(o[nb], ph, vhf[nb]);
#pragma unroll
                for (int nb = 0; nb < 8; nb++) mma_bf16(o[nb], ph, vlf[nb]);
#pragma unroll
                for (int nb = 0; nb < 8; nb++) mma_bf16(o[nb], pl, vhf[nb]);
            }
        }
        __syncthreads();
    }

    // ---- epilogue: normalize + split-write ----
    float i0 = __fdividef(1.f, l0), i1 = __fdividef(1.f, l1);
#pragma unroll
    for (int nb = 0; nb < 8; nb++) {
        size_t e0 = ((size_t)(b*SEQ + qi0) * DIM + h*HD + nb*8 + c2) >> 1;
        size_t e1 = ((size_t)(b*SEQ + qi1) * DIM + h*HD + nb*8 + c2) >> 1;
        uint32_t h0, lo0, h1, lo1;
        split2(o[nb][0] * i0, o[nb][1] * i0, h0, lo0);
        split2(o[nb][2] * i1, o[nb][3] * i1, h1, lo1);
        ((uint32_t*)Oh)[e0] = h0; ((uint32_t*)Ol)[e0] = lo0;
        ((uint32_t*)Oh)[e1] = h1; ((uint32_t*)Ol)[e1] = lo1;
    }
}

// =============================== Launch ====================================
extern "C" void kernel_launch(void* const* d_in, const int* in_sizes, int n_in,
                              void* d_out, int out_size)
{
    const float* x  = (const float*)d_in[0];
    const float* wq = (const float*)d_in[1];
    const float* wk = (const float*)d_in[2];
    const float* wv = (const float*)d_in[3];
    const float* wo = (const float*)d_in[4];
    float* out = (float*)d_out;

    __nv_bfloat16 *xh, *xl, *wqh, *wql, *wkh, *wkl, *wvh, *wvl, *woh, *wol;
    __nv_bfloat16 *Qh, *Ql, *Kh, *Kl, *Vh, *Vl, *Oh, *Ol;
    cudaGetSymbolAddress((void**)&xh,  g_xh);  cudaGetSymbolAddress((void**)&xl,  g_xl);
    cudaGetSymbolAddress((void**)&wqh, g_wqh); cudaGetSymbolAddress((void**)&wql, g_wql);
    cudaGetSymbolAddress((void**)&wkh, g_wkh); cudaGetSymbolAddress((void**)&wkl, g_wkl);
    cudaGetSymbolAddress((void**)&wvh, g_wvh); cudaGetSymbolAddress((void**)&wvl, g_wvl);
    cudaGetSymbolAddress((void**)&woh, g_woh); cudaGetSymbolAddress((void**)&wol, g_wol);
    cudaGetSymbolAddress((void**)&Qh,  g_Qh);  cudaGetSymbolAddress((void**)&Ql,  g_Ql);
    cudaGetSymbolAddress((void**)&Kh,  g_Kh);  cudaGetSymbolAddress((void**)&Kl,  g_Kl);
    cudaGetSymbolAddress((void**)&Vh,  g_Vh);  cudaGetSymbolAddress((void**)&Vl,  g_Vl);
    cudaGetSymbolAddress((void**)&Oh,  g_Oh);  cudaGetSymbolAddress((void**)&Ol,  g_Ol);

    cudaFuncSetAttribute(gemm_qkv, cudaFuncAttributeMaxDynamicSharedMemorySize, GEMM_SMEM);
    cudaFuncSetAttribute(gemm_o,   cudaFuncAttributeMaxDynamicSharedMemorySize, GEMM_SMEM);
    cudaFuncSetAttribute(attn_ps,  cudaFuncAttributeMaxDynamicSharedMemorySize, ATT_SMEM);

    dim3 blk(256);
    // one-time input splits
    split_f32<<<(MTOT*DIM/4 + 255)/256, blk>>>(x,  xh,  xl,  MTOT*DIM/4);
    split_f32<<<(DIM*DIM/4  + 255)/256, blk>>>(wq, wqh, wql, DIM*DIM/4);
    split_f32<<<(KVD*DIM/4  + 255)/256, blk>>>(wk, wkh, wkl, KVD*DIM/4);
    split_f32<<<(KVD*DIM/4  + 255)/256, blk>>>(wv, wvh, wvl, KVD*DIM/4);
    split_f32<<<(DIM*DIM/4  + 255)/256, blk>>>(wo, woh, wol, DIM*DIM/4);

    gemm_qkv<<<dim3(24, MTOT/128), blk, GEMM_SMEM>>>(
        xh, xl, wqh, wql, wkh, wkl, wvh, wvl, Qh, Ql, Kh, Kl, Vh, Vl);
    attn_ps<<<dim3(SEQ/128, NH, BATCH), blk, ATT_SMEM>>>(
        Qh, Ql, Kh, Kl, Vh, Vl, Oh, Ol);
    gemm_o<<<dim3(DIM/128, MTOT/128), blk, GEMM_SMEM>>>(
        Oh, Ol, woh, wol, out);
}

// round 7
// speedup vs baseline: 3.2460x; 1.0135x over previous
#include <cuda_runtime.h>
#include <cuda_bf16.h>
#include <cstdint>
#include <math.h>

// Problem constants
#define BATCH 2
#define SEQ   2048
#define DIM   2048
#define NH    32
#define NKV   8
#define HD    64
#define KVD   (NKV*HD)    // 512
#define MTOT  (BATCH*SEQ) // 4096

// Scratch (device globals: allocation-free) — all pre-split bf16 pairs
__device__ __nv_bfloat16 g_xh [MTOT * DIM],  g_xl [MTOT * DIM];
__device__ __nv_bfloat16 g_wqh[DIM * DIM],   g_wql[DIM * DIM];
__device__ __nv_bfloat16 g_wkh[KVD * DIM],   g_wkl[KVD * DIM];
__device__ __nv_bfloat16 g_wvh[KVD * DIM],   g_wvl[KVD * DIM];
__device__ __nv_bfloat16 g_woh[DIM * DIM],   g_wol[DIM * DIM];
__device__ __nv_bfloat16 g_Qh [MTOT * DIM],  g_Ql [MTOT * DIM];
__device__ __nv_bfloat16 g_Kh [MTOT * KVD],  g_Kl [MTOT * KVD];
__device__ __nv_bfloat16 g_Vh [MTOT * KVD],  g_Vl [MTOT * KVD];
__device__ __nv_bfloat16 g_Oh [MTOT * DIM],  g_Ol [MTOT * DIM];

// ============================ helpers ======================================
__device__ __forceinline__ uint32_t smem_u32(const void* p) {
    uint32_t a;
    asm("{ .reg .u64 t; cvta.to.shared.u64 t, %1; cvt.u32.u64 %0, t; }"
        : "=r"(a) : "l"(p));
    return a;
}
__device__ __forceinline__ void cp16(uint32_t dst, const void* src) {
    asm volatile("cp.async.cg.shared.global [%0], [%1], 16;"
                 :: "r"(dst), "l"(src) : "memory");
}
#define CP_COMMIT() asm volatile("cp.async.commit_group;" ::: "memory")
#define CP_WAIT0()  asm volatile("cp.async.wait_group 0;" ::: "memory")
#define CP_WAIT1()  asm volatile("cp.async.wait_group 1;" ::: "memory")

__device__ __forceinline__ void ldmatrix_x4(uint32_t& r0, uint32_t& r1,
                                            uint32_t& r2, uint32_t& r3,
                                            uint32_t addr) {
    asm volatile("ldmatrix.sync.aligned.m8n8.x4.shared.b16 {%0,%1,%2,%3}, [%4];"
                 : "=r"(r0), "=r"(r1), "=r"(r2), "=r"(r3) : "r"(addr));
}
__device__ __forceinline__ void ldmatrix_x4_trans(uint32_t& r0, uint32_t& r1,
                                                  uint32_t& r2, uint32_t& r3,
                                                  uint32_t addr) {
    asm volatile("ldmatrix.sync.aligned.m8n8.x4.trans.shared.b16 {%0,%1,%2,%3}, [%4];"
                 : "=r"(r0), "=r"(r1), "=r"(r2), "=r"(r3) : "r"(addr));
}
__device__ __forceinline__ void mma_bf16(float* d, const uint32_t* a,
                                         const uint32_t* b) {
    asm volatile(
        "mma.sync.aligned.m16n8k16.row.col.f32.bf16.bf16.f32 "
        "{%0,%1,%2,%3}, {%4,%5,%6,%7}, {%8,%9}, {%0,%1,%2,%3};"
        : "+f"(d[0]), "+f"(d[1]), "+f"(d[2]), "+f"(d[3])
        : "r"(a[0]), "r"(a[1]), "r"(a[2]), "r"(a[3]), "r"(b[0]), "r"(b[1]));
}

// fp32 pair -> packed (hi,lo) bf16x2
__device__ __forceinline__ void split2(float a, float b, uint32_t& hi, uint32_t& lo) {
    __nv_bfloat16 ha = __float2bfloat16(a), hb = __float2bfloat16(b);
    hi = (uint32_t)__bfloat16_as_ushort(ha) |
         ((uint32_t)__bfloat16_as_ushort(hb) << 16);
    float ra = a - __bfloat162float(ha);
    float rb = b - __bfloat162float(hb);
    uint32_t d;
    asm("cvt.rn.bf16x2.f32 %0, %1, %2;" : "=r"(d) : "f"(rb), "f"(ra));
    lo = d;
}

// exp(x*0.125) via 2^y polynomial on FMA pipe (x <= 0)
__device__ __forceinline__ float fexp2c(float x) {
    float y = fmaxf(x * 0.1803368801f, -126.f);
    float r = rintf(y);
    float f = y - r;
    float p = 1.3333558e-3f;
    p = fmaf(p, f, 9.6181291e-3f);
    p = fmaf(p, f, 5.5504109e-2f);
    p = fmaf(p, f, 2.4022651e-1f);
    p = fmaf(p, f, 6.9314718e-1f);
    p = fmaf(p, f, 1.0f);
    return p * __int_as_float(((int)r + 127) << 23);
}

// ================ fused pre-split kernel (fp32 -> hi/lo bf16) ==============
// segments (float4 units): x 2097152 | wq 1048576 | wk 262144 | wv 262144 | wo 1048576
#define SPLIT_N4 4718592
__global__ __launch_bounds__(256)
void split_all(const float* __restrict__ x,  const float* __restrict__ wq,
               const float* __restrict__ wk, const float* __restrict__ wv,
               const float* __restrict__ wo,
               __nv_bfloat16* xh,  __nv_bfloat16* xl,
               __nv_bfloat16* wqh, __nv_bfloat16* wql,
               __nv_bfloat16* wkh, __nv_bfloat16* wkl,
               __nv_bfloat16* wvh, __nv_bfloat16* wvl,
               __nv_bfloat16* woh, __nv_bfloat16* wol)
{
    int i = blockIdx.x * 256 + threadIdx.x;
    if (i >= SPLIT_N4) return;
    const float* in; __nv_bfloat16 *hi, *lo; int off;
    if (i < 2097152)      { in = x;  hi = xh;  lo = xl;  off = 0; }
    else if (i < 3145728) { in = wq; hi = wqh; lo = wql; off = 2097152; }
    else if (i < 3407872) { in = wk; hi = wkh; lo = wkl; off = 3145728; }
    else if (i < 3670016) { in = wv; hi = wvh; lo = wvl; off = 3407872; }
    else                  { in = wo; hi = woh; lo = wol; off = 3670016; }
    i -= off;
    float4 v = ((const float4*)in)[i];
    uint32_t h0, l0, h1, l1;
    split2(v.x, v.y, h0, l0);
    split2(v.z, v.w, h1, l1);
    ((uint2*)hi)[i] = make_uint2(h0, h1);
    ((uint2*)lo)[i] = make_uint2(l0, l1);
}

// ===================== pre-split bf16 GEMM body ============================
#define LDS_ 40
#define GSTG 20480
#define GEMM_SMEM (2 * GSTG * 2)   // 81920 bytes

template<int SPLIT>
__device__ __forceinline__ void gemm_body(
    const __nv_bfloat16* __restrict__ Ah_t, const __nv_bfloat16* __restrict__ Al_t,
    const __nv_bfloat16* __restrict__ Bh_t, const __nv_bfloat16* __restrict__ Bl_t,
    float* __restrict__ C, __nv_bfloat16* __restrict__ Ch,
    __nv_bfloat16* __restrict__ Cl, int ldc, int K, __nv_bfloat16* gsm)
{
    const uint32_t usm = smem_u32(gsm);
    const int tid  = threadIdx.x;
    const int lane = tid & 31;
    const int wid  = tid >> 5;
    const int wm   = wid & 1;
    const int wn   = wid >> 1;

    const __nv_bfloat16* srcs[4] = { Ah_t, Al_t, Bh_t, Bl_t };

    float acc[4][4][4];
#pragma unroll
    for (int i = 0; i < 4; i++)
#pragma unroll
        for (int j = 0; j < 4; j++)
#pragma unroll
            for (int q = 0; q < 4; q++) acc[i][j][q] = 0.f;

    const int aBase = (wm * 64 + (lane & 15)) * LDS_ + ((lane >> 4) << 3);
    const int bN    = ((lane >> 4) << 3) + (lane & 7);
    const int bK    = ((lane >> 3) & 1) << 3;
    const int bBase = (wn * 32 + bN) * LDS_ + bK;

    const int NC = K / 32;

    auto issue = [&](int k0, int st) {
        uint32_t base = usm + (uint32_t)(st * GSTG * 2);
#pragma unroll
        for (int j = 0; j < 8; j++) {
            int s = tid + (j << 8);
            int arr = s >> 9, r = (s >> 2) & 127, c = s & 3;
            cp16(base + (uint32_t)((arr * 5120 + r * LDS_ + c * 8) * 2),
                 srcs[arr] + (size_t)r * K + k0 + c * 8);
        }
    };

    issue(0, 0);
    CP_COMMIT();

    for (int cIt = 0; cIt < NC; cIt++) {
        const int st = cIt & 1;
        if (cIt + 1 < NC) {
            issue((cIt + 1) * 32, st ^ 1);
            CP_COMMIT();
            CP_WAIT1();
        } else {
            CP_WAIT0();
        }
        __syncthreads();

        const uint32_t sb  = usm + (uint32_t)(st * GSTG * 2);
        const uint32_t uAh = sb, uAl = sb + 5120 * 2;
        const uint32_t uBh = sb + 10240 * 2, uBl = sb + 15360 * 2;

#pragma unroll
        for (int kk = 0; kk < 2; kk++) {
            const int ke = kk << 4;
            uint32_t bh[4][2], bl[4][2];
#pragma unroll
            for (int g = 0; g < 2; g++) {
                uint32_t addr = (uint32_t)((bBase + g * 16 * LDS_ + ke) * 2);
                ldmatrix_x4(bh[g*2][0], bh[g*2][1], bh[g*2+1][0], bh[g*2+1][1],
                            uBh + addr);
                ldmatrix_x4(bl[g*2][0], bl[g*2][1], bl[g*2+1][0], bl[g*2+1][1],
                            uBl + addr);
            }
#pragma unroll
            for (int mi = 0; mi < 4; mi++) {
                uint32_t ah[4], al[4];
                uint32_t addr = (uint32_t)((aBase + mi * 16 * LDS_ + ke) * 2);
                ldmatrix_x4(ah[0], ah[1], ah[2], ah[3], uAh + addr);
                ldmatrix_x4(al[0], al[1], al[2], al[3], uAl + addr);
#pragma unroll
                for (int ni = 0; ni < 4; ni++) mma_bf16(acc[mi][ni], ah, bh[ni]);
#pragma unroll
                for (int ni = 0; ni < 4; ni++) mma_bf16(acc[mi][ni], ah, bl[ni]);
#pragma unroll
                for (int ni = 0; ni < 4; ni++) mma_bf16(acc[mi][ni], al, bh[ni]);
            }
        }
        __syncthreads();
    }

    const int erow = lane >> 2;
    const int ecol = (lane & 3) << 1;
#pragma unroll
    for (int mi = 0; mi < 4; mi++) {
#pragma unroll
        for (int ni = 0; ni < 4; ni++) {
            int r0 = wm * 64 + mi * 16 + erow;
            int cc = wn * 32 + ni * 8 + ecol;
            if (SPLIT) {
                uint32_t h0, l0, h1, l1;
                split2(acc[mi][ni][0], acc[mi][ni][1], h0, l0);
                split2(acc[mi][ni][2], acc[mi][ni][3], h1, l1);
                size_t i0 = ((size_t)r0 * ldc + cc) >> 1;
                size_t i1 = ((size_t)(r0 + 8) * ldc + cc) >> 1;
                ((uint32_t*)Ch)[i0] = h0; ((uint32_t*)Cl)[i0] = l0;
                ((uint32_t*)Ch)[i1] = h1; ((uint32_t*)Cl)[i1] = l1;
            } else {
                *(float2*)&C[(size_t)r0 * ldc + cc] =
                    make_float2(acc[mi][ni][0], acc[mi][ni][1]);
                *(float2*)&C[(size_t)(r0 + 8) * ldc + cc] =
                    make_float2(acc[mi][ni][2], acc[mi][ni][3]);
            }
        }
    }
}

// Fused Q/K/V projection
__global__ __launch_bounds__(256, 2)
void gemm_qkv(const __nv_bfloat16* __restrict__ xh, const __nv_bfloat16* __restrict__ xl,
              const __nv_bfloat16* __restrict__ wqh, const __nv_bfloat16* __restrict__ wql,
              const __nv_bfloat16* __restrict__ wkh, const __nv_bfloat16* __restrict__ wkl,
              const __nv_bfloat16* __restrict__ wvh, const __nv_bfloat16* __restrict__ wvl,
              __nv_bfloat16* __restrict__ Qh, __nv_bfloat16* __restrict__ Ql,
              __nv_bfloat16* __restrict__ Kh, __nv_bfloat16* __restrict__ Kl,
              __nv_bfloat16* __restrict__ Vh, __nv_bfloat16* __restrict__ Vl)
{
    extern __shared__ __nv_bfloat16 gsm[];
    const int nt = blockIdx.x;
    const int bm = blockIdx.y * 128;
    const __nv_bfloat16 *Bh, *Bl;
    __nv_bfloat16 *Ch, *Cl;
    int ldc, bn;
    if (nt < 16)      { Bh = wqh; Bl = wql; Ch = Qh; Cl = Ql; ldc = DIM; bn = nt * 128; }
    else if (nt < 20) { Bh = wkh; Bl = wkl; Ch = Kh; Cl = Kl; ldc = KVD; bn = (nt - 16) * 128; }
    else              { Bh = wvh; Bl = wvl; Ch = Vh; Cl = Vl; ldc = KVD; bn = (nt - 20) * 128; }
    gemm_body<1>(xh + (size_t)bm * DIM, xl + (size_t)bm * DIM,
                 Bh + (size_t)bn * DIM, Bl + (size_t)bn * DIM,
                 nullptr,
                 Ch + (size_t)bm * ldc + bn, Cl + (size_t)bm * ldc + bn,
                 ldc, DIM, gsm);
}

__global__ __launch_bounds__(256, 2)
void gemm_o(const __nv_bfloat16* __restrict__ Ah, const __nv_bfloat16* __restrict__ Al,
            const __nv_bfloat16* __restrict__ Bh, const __nv_bfloat16* __restrict__ Bl,
            float* __restrict__ C)
{
    extern __shared__ __nv_bfloat16 gsm[];
    const int bm = blockIdx.y * 128, bn = blockIdx.x * 128;
    gemm_body<0>(Ah + (size_t)bm * DIM, Al + (size_t)bm * DIM,
                 Bh + (size_t)bn * DIM, Bl + (size_t)bn * DIM,
                 C + (size_t)bm * DIM + bn, nullptr, nullptr,
                 DIM, DIM, gsm);
}

// ===== Flash attention: 128 q x 128 kv tiles, softmax amortized over 128 ====
#define LDQ 72
// elems: Q hi+lo 18432 | 2 stages x (Kh,Kl,Vh,Vl @ 128*72 = 9216 each) 36864
#define AKV2  36864
#define ATT_SMEM ((18432 + 2 * AKV2) * 2)   // 184320 bytes

__global__ __launch_bounds__(256, 1)
void attn_ps(const __nv_bfloat16* __restrict__ Qh_g, const __nv_bfloat16* __restrict__ Ql_g,
             const __nv_bfloat16* __restrict__ Kh_g, const __nv_bfloat16* __restrict__ Kl_g,
             const __nv_bfloat16* __restrict__ Vh_g, const __nv_bfloat16* __restrict__ Vl_g,
             __nv_bfloat16* __restrict__ Oh, __nv_bfloat16* __restrict__ Ol)
{
    extern __shared__ __nv_bfloat16 sm[];
    const uint32_t usm = smem_u32(sm);

    const int b = blockIdx.z, h = blockIdx.y;
    const int qt = (int)gridDim.x - 1 - (int)blockIdx.x;   // heavy tiles first
    const int tid = threadIdx.x, lane = tid & 31, w = tid >> 5;
    const int kvh = h >> 2;
    const int qBase = qt * 128;
    const int wq0 = qBase + 16 * w;

    const __nv_bfloat16* kvsrc[4] = {
        Kh_g + (size_t)(b * SEQ) * KVD + kvh * HD,
        Kl_g + (size_t)(b * SEQ) * KVD + kvh * HD,
        Vh_g + (size_t)(b * SEQ) * KVD + kvh * HD,
        Vl_g + (size_t)(b * SEQ) * KVD + kvh * HD };

    // --- issue Q ---
    {
        const __nv_bfloat16* qs[2] = {
            Qh_g + (size_t)(b * SEQ + qBase) * DIM + h * HD,
            Ql_g + (size_t)(b * SEQ + qBase) * DIM + h * HD };
#pragma unroll
        for (int j = 0; j < 8; j++) {
            int s = tid + (j << 8);
            int arr = s >> 10, r = (s >> 3) & 127, c = s & 7;
            cp16(usm + (uint32_t)((arr * 9216 + r * LDQ + c * 8) * 2),
                 qs[arr] + (size_t)r * DIM + c * 8);
        }
        CP_COMMIT();
    }

    // KV tile: 128 rows x 64 dims, 4 arrays -> 4096 cp16 chunks (16/thread)
    auto issue_kv = [&](int j, int st) {
        int kvBase = j * 128;
        uint32_t base = usm + (uint32_t)((18432 + st * AKV2) * 2);
#pragma unroll
        for (int q = 0; q < 16; q++) {
            int s = tid + (q << 8);
            int arr = s >> 10, r = (s >> 3) & 127, c = s & 7;
            cp16(base + (uint32_t)((arr * 9216 + r * LDQ + c * 8) * 2),
                 kvsrc[arr] + (size_t)(kvBase + r) * KVD + c * 8);
        }
    };

    const int ntiles = qt + 1;
    issue_kv(0, 0);
    CP_COMMIT();

    CP_WAIT1();
    __syncthreads();

    uint32_t qh[4][4], ql[4][4];
    {
        int off0 = (16*w + (lane & 15)) * LDQ + ((lane >> 4) << 3);
#pragma unroll
        for (int kb = 0; kb < 4; kb++) {
            uint32_t off = (uint32_t)((off0 + kb * 16) * 2);
            ldmatrix_x4(qh[kb][0], qh[kb][1], qh[kb][2], qh[kb][3], usm + off);
            ldmatrix_x4(ql[kb][0], ql[kb][1], ql[kb][2], ql[kb][3],
                        usm + (uint32_t)(9216 * 2) + off);
        }
    }

    float o[8][4];
#pragma unroll
    for (int nb = 0; nb < 8; nb++)
#pragma unroll
        for (int q = 0; q < 4; q++) o[nb][q] = 0.f;
    float m0 = -3e38f, m1 = -3e38f, l0 = 0.f, l1 = 0.f;

    const int bN = ((lane >> 4) << 3) + (lane & 7);
    const int bK = ((lane >> 3) & 1) << 3;
    const int vRow = lane & 15, vCol = (lane >> 4) << 3;
    const int r0   = lane >> 2;
    const int c2   = (lane & 3) << 1;
    const int qi0  = wq0 + r0, qi1 = qi0 + 8;

    for (int j = 0; j < ntiles; j++) {
        const int kvBase = j * 128;
        const int st = j & 1;
        if (j + 1 < ntiles) {
            issue_kv(j + 1, st ^ 1);
            CP_COMMIT();
            CP_WAIT1();
        } else {
            CP_WAIT0();
        }
        __syncthreads();

        if (kvBase <= wq0 + 15) {
            const uint32_t kvb = usm + (uint32_t)((18432 + st * AKV2) * 2);
            const uint32_t uKh = kvb, uKl = kvb + 9216 * 2;
            const uint32_t uVh = kvb + 18432 * 2, uVl = kvb + 27648 * 2;

            // ---- S = Q K^T over 16 n-blocks (two 64-col halves) ----
            float sa[16][4];
#pragma unroll
            for (int nb = 0; nb < 16; nb++)
#pragma unroll
                for (int q = 0; q < 4; q++) sa[nb][q] = 0.f;

#pragma unroll
            for (int hf = 0; hf < 2; hf++) {
#pragma unroll
                for (int kb = 0; kb < 4; kb++) {
                    uint32_t bhf[8][2], blf[8][2];
#pragma unroll
                    for (int g = 0; g < 4; g++) {
                        uint32_t off = (uint32_t)((((hf*64 + g*16) + bN) * LDQ
                                                  + kb*16 + bK) * 2);
                        ldmatrix_x4(bhf[2*g][0], bhf[2*g][1],
                                    bhf[2*g+1][0], bhf[2*g+1][1], uKh + off);
                        ldmatrix_x4(blf[2*g][0], blf[2*g][1],
                                    blf[2*g+1][0], blf[2*g+1][1], uKl + off);
                    }
                    float* sp = &sa[hf*8][0];
#pragma unroll
                    for (int nb = 0; nb < 8; nb++) mma_bf16(sp + nb*4, qh[kb], bhf[nb]);
#pragma unroll
                    for (int nb = 0; nb < 8; nb++) mma_bf16(sp + nb*4, qh[kb], blf[nb]);
#pragma unroll
                    for (int nb = 0; nb < 8; nb++) mma_bf16(sp + nb*4, ql[kb], bhf[nb]);
                }
            }

            // ---- causal mask (boundary tile only) ----
            if (kvBase + 127 > wq0) {
#pragma unroll
                for (int nb = 0; nb < 16; nb++) {
                    int col = kvBase + nb * 8 + c2;
                    if (col     > qi0) sa[nb][0] = -3e38f;
                    if (col + 1 > qi0) sa[nb][1] = -3e38f;
                    if (col     > qi1) sa[nb][2] = -3e38f;
                    if (col + 1 > qi1) sa[nb][3] = -3e38f;
                }
            }

            // ---- online softmax (one pass over 128 cols) ----
            float mx0 = -3e38f, mx1 = -3e38f;
#pragma unroll
            for (int nb = 0; nb < 16; nb++) {
                mx0 = fmaxf(mx0, fmaxf(sa[nb][0], sa[nb][1]));
                mx1 = fmaxf(mx1, fmaxf(sa[nb][2], sa[nb][3]));
            }
            mx0 = fmaxf(mx0, __shfl_xor_sync(0xffffffffu, mx0, 1));
            mx0 = fmaxf(mx0, __shfl_xor_sync(0xffffffffu, mx0, 2));
            mx1 = fmaxf(mx1, __shfl_xor_sync(0xffffffffu, mx1, 1));
            mx1 = fmaxf(mx1, __shfl_xor_sync(0xffffffffu, mx1, 2));
            float mn0 = fmaxf(m0, mx0), mn1 = fmaxf(m1, mx1);
            float a0 = fexp2c(m0 - mn0), a1 = fexp2c(m1 - mn1);
            m0 = mn0; m1 = mn1;

            float s0 = 0.f, s1 = 0.f;
#pragma unroll
            for (int nb = 0; nb < 16; nb++) {
                sa[nb][0] = fexp2c(sa[nb][0] - mn0); s0 += sa[nb][0];
                sa[nb][1] = fexp2c(sa[nb][1] - mn0); s0 += sa[nb][1];
                sa[nb][2] = fexp2c(sa[nb][2] - mn1); s1 += sa[nb][2];
                sa[nb][3] = fexp2c(sa[nb][3] - mn1); s1 += sa[nb][3];
            }
            s0 += __shfl_xor_sync(0xffffffffu, s0, 1);
            s0 += __shfl_xor_sync(0xffffffffu, s0, 2);
            s1 += __shfl_xor_sync(0xffffffffu, s1, 1);
            s1 += __shfl_xor_sync(0xffffffffu, s1, 2);
            l0 = l0 * a0 + s0;
            l1 = l1 * a1 + s1;
#pragma unroll
            for (int nb = 0; nb < 8; nb++) {
                o[nb][0] *= a0; o[nb][1] *= a0;
                o[nb][2] *= a1; o[nb][3] *= a1;
            }

            // ---- O += P V over 8 k16-blocks ----
#pragma unroll
            for (int jk = 0; jk < 8; jk++) {
                uint32_t ph[4], pl[4];
                split2(sa[2*jk][0],   sa[2*jk][1],   ph[0], pl[0]);
                split2(sa[2*jk][2],   sa[2*jk][3],   ph[1], pl[1]);
                split2(sa[2*jk+1][0], sa[2*jk+1][1], ph[2], pl[2]);
                split2(sa[2*jk+1][2], sa[2*jk+1][3], ph[3], pl[3]);
                uint32_t vhf[8][2], vlf[8][2];
#pragma unroll
                for (int g = 0; g < 4; g++) {
                    uint32_t off = (uint32_t)(((jk*16 + vRow) * LDQ + g*16 + vCol) * 2);
                    ldmatrix_x4_trans(vhf[2*g][0], vhf[2*g][1],
                                      vhf[2*g+1][0], vhf[2*g+1][1], uVh + off);
                    ldmatrix_x4_trans(vlf[2*g][0], vlf[2*g][1],
                                      vlf[2*g+1][0], vlf[2*g+1][1], uVl + off);
                }
#pragma unroll
                for (int nb = 0; nb < 8; nb++) mma_bf16(o[nb], ph, vhf[nb]);
#pragma unroll
                for (int nb = 0; nb < 8; nb++) mma_bf16(o[nb], ph, vlf[nb]);
#pragma unroll
                for (int nb = 0; nb < 8; nb++) mma_bf16(o[nb], pl, vhf[nb]);
            }
        }
        __syncthreads();
    }

    // ---- epilogue: normalize + split-write ----
    float i0 = __fdividef(1.f, l0), i1 = __fdividef(1.f, l1);
#pragma unroll
    for (int nb = 0; nb < 8; nb++) {
        size_t e0 = ((size_t)(b*SEQ + qi0) * DIM + h*HD + nb*8 + c2) >> 1;
        size_t e1 = ((size_t)(b*SEQ + qi1) * DIM + h*HD + nb*8 + c2) >> 1;
        uint32_t h0, lo0, h1, lo1;
        split2(o[nb][0] * i0, o[nb][1] * i0, h0, lo0);
        split2(o[nb][2] * i1, o[nb][3] * i1, h1, lo1);
        ((uint32_t*)Oh)[e0] = h0; ((uint32_t*)Ol)[e0] = lo0;
        ((uint32_t*)Oh)[e1] = h1; ((uint32_t*)Ol)[e1] = lo1;
    }
}

// =============================== Launch ====================================
extern "C" void kernel_launch(void* const* d_in, const int* in_sizes, int n_in,
                              void* d_out, int out_size)
{
    const float* x  = (const float*)d_in[0];
    const float* wq = (const float*)d_in[1];
    const float* wk = (const float*)d_in[2];
    const float* wv = (const float*)d_in[3];
    const float* wo = (const float*)d_in[4];
    float* out = (float*)d_out;

    __nv_bfloat16 *xh, *xl, *wqh, *wql, *wkh, *wkl, *wvh, *wvl, *woh, *wol;
    __nv_bfloat16 *Qh, *Ql, *Kh, *Kl, *Vh, *Vl, *Oh, *Ol;
    cudaGetSymbolAddress((void**)&xh,  g_xh);  cudaGetSymbolAddress((void**)&xl,  g_xl);
    cudaGetSymbolAddress((void**)&wqh, g_wqh); cudaGetSymbolAddress((void**)&wql, g_wql);
    cudaGetSymbolAddress((void**)&wkh, g_wkh); cudaGetSymbolAddress((void**)&wkl, g_wkl);
    cudaGetSymbolAddress((void**)&wvh, g_wvh); cudaGetSymbolAddress((void**)&wvl, g_wvl);
    cudaGetSymbolAddress((void**)&woh, g_woh); cudaGetSymbolAddress((void**)&wol, g_wol);
    cudaGetSymbolAddress((void**)&Qh,  g_Qh);  cudaGetSymbolAddress((void**)&Ql,  g_Ql);
    cudaGetSymbolAddress((void**)&Kh,  g_Kh);  cudaGetSymbolAddress((void**)&Kl,  g_Kl);
    cudaGetSymbolAddress((void**)&Vh,  g_Vh);  cudaGetSymbolAddress((void**)&Vl,  g_Vl);
    cudaGetSymbolAddress((void**)&Oh,  g_Oh);  cudaGetSymbolAddress((void**)&Ol,  g_Ol);

    cudaFuncSetAttribute(gemm_qkv, cudaFuncAttributeMaxDynamicSharedMemorySize, GEMM_SMEM);
    cudaFuncSetAttribute(gemm_o,   cudaFuncAttributeMaxDynamicSharedMemorySize, GEMM_SMEM);
    cudaFuncSetAttribute(attn_ps,  cudaFuncAttributeMaxDynamicSharedMemorySize, ATT_SMEM);

    dim3 blk(256);
    split_all<<<(SPLIT_N4 + 255)/256, blk>>>(x, wq, wk, wv, wo,
        xh, xl, wqh, wql, wkh, wkl, wvh, wvl, woh, wol);

    gemm_qkv<<<dim3(24, MTOT/128), blk, GEMM_SMEM>>>(
        xh, xl, wqh, wql, wkh, wkl, wvh, wvl, Qh, Ql, Kh, Kl, Vh, Vl);
    attn_ps<<<dim3(SEQ/128, NH, BATCH), blk, ATT_SMEM>>>(
        Qh, Ql, Kh, Kl, Vh, Vl, Oh, Ol);
    gemm_o<<<dim3(DIM/128, MTOT/128), blk, GEMM_SMEM>>>(
        Oh, Ol, woh, wol, out);
}

// round 8
// speedup vs baseline: 3.5442x; 1.0919x over previous
#include <cuda_runtime.h>
#include <cuda_bf16.h>
#include <cstdint>
#include <math.h>

// Problem constants
#define BATCH 2
#define SEQ   2048
#define DIM   2048
#define NH    32
#define NKV   8
#define HD    64
#define KVD   (NKV*HD)    // 512
#define MTOT  (BATCH*SEQ) // 4096

// Scratch (device globals: allocation-free) — all pre-split bf16 pairs
__device__ __nv_bfloat16 g_xh [MTOT * DIM],  g_xl [MTOT * DIM];
__device__ __nv_bfloat16 g_wqh[DIM * DIM],   g_wql[DIM * DIM];
__device__ __nv_bfloat16 g_wkh[KVD * DIM],   g_wkl[KVD * DIM];
__device__ __nv_bfloat16 g_wvh[KVD * DIM],   g_wvl[KVD * DIM];
__device__ __nv_bfloat16 g_woh[DIM * DIM],   g_wol[DIM * DIM];
__device__ __nv_bfloat16 g_Qh [MTOT * DIM],  g_Ql [MTOT * DIM];
__device__ __nv_bfloat16 g_Kh [MTOT * KVD],  g_Kl [MTOT * KVD];
__device__ __nv_bfloat16 g_Vh [MTOT * KVD],  g_Vl [MTOT * KVD];
__device__ __nv_bfloat16 g_Oh [MTOT * DIM],  g_Ol [MTOT * DIM];

// ============================ helpers ======================================
__device__ __forceinline__ uint32_t smem_u32(const void* p) {
    uint32_t a;
    asm("{ .reg .u64 t; cvta.to.shared.u64 t, %1; cvt.u32.u64 %0, t; }"
        : "=r"(a) : "l"(p));
    return a;
}
__device__ __forceinline__ void cp16(uint32_t dst, const void* src) {
    asm volatile("cp.async.cg.shared.global [%0], [%1], 16;"
                 :: "r"(dst), "l"(src) : "memory");
}
#define CP_COMMIT() asm volatile("cp.async.commit_group;" ::: "memory")
#define CP_WAIT0()  asm volatile("cp.async.wait_group 0;" ::: "memory")
#define CP_WAIT1()  asm volatile("cp.async.wait_group 1;" ::: "memory")

__device__ __forceinline__ void ldmatrix_x4(uint32_t& r0, uint32_t& r1,
                                            uint32_t& r2, uint32_t& r3,
                                            uint32_t addr) {
    asm volatile("ldmatrix.sync.aligned.m8n8.x4.shared.b16 {%0,%1,%2,%3}, [%4];"
                 : "=r"(r0), "=r"(r1), "=r"(r2), "=r"(r3) : "r"(addr));
}
__device__ __forceinline__ void ldmatrix_x4_trans(uint32_t& r0, uint32_t& r1,
                                                  uint32_t& r2, uint32_t& r3,
                                                  uint32_t addr) {
    asm volatile("ldmatrix.sync.aligned.m8n8.x4.trans.shared.b16 {%0,%1,%2,%3}, [%4];"
                 : "=r"(r0), "=r"(r1), "=r"(r2), "=r"(r3) : "r"(addr));
}
__device__ __forceinline__ void mma_bf16(float* d, const uint32_t* a,
                                         const uint32_t* b) {
    asm volatile(
        "mma.sync.aligned.m16n8k16.row.col.f32.bf16.bf16.f32 "
        "{%0,%1,%2,%3}, {%4,%5,%6,%7}, {%8,%9}, {%0,%1,%2,%3};"
        : "+f"(d[0]), "+f"(d[1]), "+f"(d[2]), "+f"(d[3])
        : "r"(a[0]), "r"(a[1]), "r"(a[2]), "r"(a[3]), "r"(b[0]), "r"(b[1]));
}

// fp32 pair -> packed (hi,lo) bf16x2
__device__ __forceinline__ void split2(float a, float b, uint32_t& hi, uint32_t& lo) {
    __nv_bfloat16 ha = __float2bfloat16(a), hb = __float2bfloat16(b);
    hi = (uint32_t)__bfloat16_as_ushort(ha) |
         ((uint32_t)__bfloat16_as_ushort(hb) << 16);
    float ra = a - __bfloat162float(ha);
    float rb = b - __bfloat162float(hb);
    uint32_t d;
    asm("cvt.rn.bf16x2.f32 %0, %1, %2;" : "=r"(d) : "f"(rb), "f"(ra));
    lo = d;
}

// exp(x*0.125) via 2^y polynomial on FMA pipe (x <= 0)
__device__ __forceinline__ float fexp2c(float x) {
    float y = fmaxf(x * 0.1803368801f, -126.f);
    float r = rintf(y);
    float f = y - r;
    float p = 1.3333558e-3f;
    p = fmaf(p, f, 9.6181291e-3f);
    p = fmaf(p, f, 5.5504109e-2f);
    p = fmaf(p, f, 2.4022651e-1f);
    p = fmaf(p, f, 6.9314718e-1f);
    p = fmaf(p, f, 1.0f);
    return p * __int_as_float(((int)r + 127) << 23);
}

// XOR swizzle for 64B-wide rows: chunk slot = c8 ^ (row & 7); conflict-free
// for 8-row ldmatrix reads and perfectly-pipelined cp.async writes.
__device__ __forceinline__ uint32_t swz(uint32_t off) {
    return off ^ (((off >> 6) & 7u) << 4);
}

// ================ fused pre-split kernel (fp32 -> hi/lo bf16) ==============
#define SPLIT_N4 4718592
__global__ __launch_bounds__(256)
void split_all(const float* __restrict__ x,  const float* __restrict__ wq,
               const float* __restrict__ wk, const float* __restrict__ wv,
               const float* __restrict__ wo,
               __nv_bfloat16* xh,  __nv_bfloat16* xl,
               __nv_bfloat16* wqh, __nv_bfloat16* wql,
               __nv_bfloat16* wkh, __nv_bfloat16* wkl,
               __nv_bfloat16* wvh, __nv_bfloat16* wvl,
               __nv_bfloat16* woh, __nv_bfloat16* wol)
{
    int i = blockIdx.x * 256 + threadIdx.x;
    if (i >= SPLIT_N4) return;
    const float* in; __nv_bfloat16 *hi, *lo; int off;
    if (i < 2097152)      { in = x;  hi = xh;  lo = xl;  off = 0; }
    else if (i < 3145728) { in = wq; hi = wqh; lo = wql; off = 2097152; }
    else if (i < 3407872) { in = wk; hi = wkh; lo = wkl; off = 3145728; }
    else if (i < 3670016) { in = wv; hi = wvh; lo = wvl; off = 3407872; }
    else                  { in = wo; hi = woh; lo = wol; off = 3670016; }
    i -= off;
    float4 v = ((const float4*)in)[i];
    uint32_t h0, l0, h1, l1;
    split2(v.x, v.y, h0, l0);
    split2(v.z, v.w, h1, l1);
    ((uint2*)hi)[i] = make_uint2(h0, h1);
    ((uint2*)lo)[i] = make_uint2(l0, l1);
}

// ============== pre-split bf16 GEMM: swizzled 3-stage pipeline =============
// Stage: Ah|Al|Bh|Bl, each 128 rows x 32 cols bf16 = 8192 B -> 32768 B/stage.
#define GSTG 32768
#define GEMM_SMEM (3 * GSTG)   // 98304 bytes

template<int SPLIT>
__device__ __forceinline__ void gemm_body(
    const __nv_bfloat16* __restrict__ Ah_t, const __nv_bfloat16* __restrict__ Al_t,
    const __nv_bfloat16* __restrict__ Bh_t, const __nv_bfloat16* __restrict__ Bl_t,
    float* __restrict__ C, __nv_bfloat16* __restrict__ Ch,
    __nv_bfloat16* __restrict__ Cl, int ldc, int K, __nv_bfloat16* gsm)
{
    const uint32_t usm = smem_u32(gsm);
    const int tid  = threadIdx.x;
    const int lane = tid & 31;
    const int wid  = tid >> 5;
    const int wm   = wid & 1;
    const int wn   = wid >> 1;

    const __nv_bfloat16* srcs[4] = { Ah_t, Al_t, Bh_t, Bl_t };

    float acc[4][4][4];
#pragma unroll
    for (int i = 0; i < 4; i++)
#pragma unroll
        for (int j = 0; j < 4; j++)
#pragma unroll
            for (int q = 0; q < 4; q++) acc[i][j][q] = 0.f;

    // per-lane ldmatrix components (byte offsets within a stage array)
    const int aRow = wm * 64 + (lane & 15);            // + mi*16
    const int aCol = (lane >> 4) << 4;                 // bytes; + kk*32
    const int bRow = wn * 32 + ((lane >> 4) << 3) + (lane & 7);  // + g*16
    const int bCol = ((lane >> 3) & 1) << 4;           // bytes; + kk*32

    const int NC = K / 32;

    auto issue = [&](int k0, uint32_t base) {
#pragma unroll
        for (int j = 0; j < 8; j++) {
            int s   = tid + (j << 8);       // 0..2047 16B-chunks
            int arr = s >> 9;               // 0..3
            int w5  = s & 511;
            int r   = w5 >> 2;              // row 0..127
            int c8  = w5 & 3;               // 16B chunk in row
            cp16(base + (uint32_t)(arr * 8192) + swz((uint32_t)(r * 64 + c8 * 16)),
                 srcs[arr] + (size_t)r * K + k0 + c8 * 8);
        }
    };

    issue(0, usm);         CP_COMMIT();
    issue(32, usm + GSTG); CP_COMMIT();

    for (int c = 0; c < NC; c++) {
        CP_WAIT1();               // stage c arrived (c+1 may be in flight)
        __syncthreads();          // all warps done with stage (c-1)%3
        if (c + 2 < NC)
            issue((c + 2) * 32, usm + (uint32_t)(((c + 2) % 3) * GSTG));
        CP_COMMIT();              // unconditional: keeps group accounting fixed

        const uint32_t sb = usm + (uint32_t)((c % 3) * GSTG);
#pragma unroll
        for (int kk = 0; kk < 2; kk++) {
            const int kc = kk * 32;     // byte offset of k16 block
            uint32_t bh[4][2], bl[4][2];
#pragma unroll
            for (int g = 0; g < 2; g++) {
                uint32_t off = swz((uint32_t)((bRow + g * 16) * 64 + bCol + kc));
                ldmatrix_x4(bh[g*2][0], bh[g*2][1], bh[g*2+1][0], bh[g*2+1][1],
                            sb + 16384 + off);
                ldmatrix_x4(bl[g*2][0], bl[g*2][1], bl[g*2+1][0], bl[g*2+1][1],
                            sb + 24576 + off);
            }
#pragma unroll
            for (int mi = 0; mi < 4; mi++) {
                uint32_t ah[4], al[4];
                uint32_t off = swz((uint32_t)((aRow + mi * 16) * 64 + aCol + kc));
                ldmatrix_x4(ah[0], ah[1], ah[2], ah[3], sb + off);
                ldmatrix_x4(al[0], al[1], al[2], al[3], sb + 8192 + off);
#pragma unroll
                for (int ni = 0; ni < 4; ni++) mma_bf16(acc[mi][ni], ah, bh[ni]);
#pragma unroll
                for (int ni = 0; ni < 4; ni++) mma_bf16(acc[mi][ni], ah, bl[ni]);
#pragma unroll
                for (int ni = 0; ni < 4; ni++) mma_bf16(acc[mi][ni], al, bh[ni]);
            }
        }
    }

    const int erow = lane >> 2;
    const int ecol = (lane & 3) << 1;
#pragma unroll
    for (int mi = 0; mi < 4; mi++) {
#pragma unroll
        for (int ni = 0; ni < 4; ni++) {
            int r0 = wm * 64 + mi * 16 + erow;
            int cc = wn * 32 + ni * 8 + ecol;
            if (SPLIT) {
                uint32_t h0, l0, h1, l1;
                split2(acc[mi][ni][0], acc[mi][ni][1], h0, l0);
                split2(acc[mi][ni][2], acc[mi][ni][3], h1, l1);
                size_t i0 = ((size_t)r0 * ldc + cc) >> 1;
                size_t i1 = ((size_t)(r0 + 8) * ldc + cc) >> 1;
                ((uint32_t*)Ch)[i0] = h0; ((uint32_t*)Cl)[i0] = l0;
                ((uint32_t*)Ch)[i1] = h1; ((uint32_t*)Cl)[i1] = l1;
            } else {
                *(float2*)&C[(size_t)r0 * ldc + cc] =
                    make_float2(acc[mi][ni][0], acc[mi][ni][1]);
                *(float2*)&C[(size_t)(r0 + 8) * ldc + cc] =
                    make_float2(acc[mi][ni][2], acc[mi][ni][3]);
            }
        }
    }
}

// Fused Q/K/V projection
__global__ __launch_bounds__(256, 2)
void gemm_qkv(const __nv_bfloat16* __restrict__ xh, const __nv_bfloat16* __restrict__ xl,
              const __nv_bfloat16* __restrict__ wqh, const __nv_bfloat16* __restrict__ wql,
              const __nv_bfloat16* __restrict__ wkh, const __nv_bfloat16* __restrict__ wkl,
              const __nv_bfloat16* __restrict__ wvh, const __nv_bfloat16* __restrict__ wvl,
              __nv_bfloat16* __restrict__ Qh, __nv_bfloat16* __restrict__ Ql,
              __nv_bfloat16* __restrict__ Kh, __nv_bfloat16* __restrict__ Kl,
              __nv_bfloat16* __restrict__ Vh, __nv_bfloat16* __restrict__ Vl)
{
    extern __shared__ __nv_bfloat16 gsm[];
    const int nt = blockIdx.x;
    const int bm = blockIdx.y * 128;
    const __nv_bfloat16 *Bh, *Bl;
    __nv_bfloat16 *Ch, *Cl;
    int ldc, bn;
    if (nt < 16)      { Bh = wqh; Bl = wql; Ch = Qh; Cl = Ql; ldc = DIM; bn = nt * 128; }
    else if (nt < 20) { Bh = wkh; Bl = wkl; Ch = Kh; Cl = Kl; ldc = KVD; bn = (nt - 16) * 128; }
    else              { Bh = wvh; Bl = wvl; Ch = Vh; Cl = Vl; ldc = KVD; bn = (nt - 20) * 128; }
    gemm_body<1>(xh + (size_t)bm * DIM, xl + (size_t)bm * DIM,
                 Bh + (size_t)bn * DIM, Bl + (size_t)bn * DIM,
                 nullptr,
                 Ch + (size_t)bm * ldc + bn, Cl + (size_t)bm * ldc + bn,
                 ldc, DIM, gsm);
}

__global__ __launch_bounds__(256, 2)
void gemm_o(const __nv_bfloat16* __restrict__ Ah, const __nv_bfloat16* __restrict__ Al,
            const __nv_bfloat16* __restrict__ Bh, const __nv_bfloat16* __restrict__ Bl,
            float* __restrict__ C)
{
    extern __shared__ __nv_bfloat16 gsm[];
    const int bm = blockIdx.y * 128, bn = blockIdx.x * 128;
    gemm_body<0>(Ah + (size_t)bm * DIM, Al + (size_t)bm * DIM,
                 Bh + (size_t)bn * DIM, Bl + (size_t)bn * DIM,
                 C + (size_t)bm * DIM + bn, nullptr, nullptr,
                 DIM, DIM, gsm);
}

// ===== Flash attention: 128 q x 128 kv tiles, softmax amortized over 128 ====
#define LDQ 72
#define AKV2  36864
#define ATT_SMEM ((18432 + 2 * AKV2) * 2)   // 184320 bytes

__global__ __launch_bounds__(256, 1)
void attn_ps(const __nv_bfloat16* __restrict__ Qh_g, const __nv_bfloat16* __restrict__ Ql_g,
             const __nv_bfloat16* __restrict__ Kh_g, const __nv_bfloat16* __restrict__ Kl_g,
             const __nv_bfloat16* __restrict__ Vh_g, const __nv_bfloat16* __restrict__ Vl_g,
             __nv_bfloat16* __restrict__ Oh, __nv_bfloat16* __restrict__ Ol)
{
    extern __shared__ __nv_bfloat16 sm[];
    const uint32_t usm = smem_u32(sm);

    const int b = blockIdx.z, h = blockIdx.y;
    const int qt = (int)gridDim.x - 1 - (int)blockIdx.x;
    const int tid = threadIdx.x, lane = tid & 31, w = tid >> 5;
    const int kvh = h >> 2;
    const int qBase = qt * 128;
    const int wq0 = qBase + 16 * w;

    const __nv_bfloat16* kvsrc[4] = {
        Kh_g + (size_t)(b * SEQ) * KVD + kvh * HD,
        Kl_g + (size_t)(b * SEQ) * KVD + kvh * HD,
        Vh_g + (size_t)(b * SEQ) * KVD + kvh * HD,
        Vl_g + (size_t)(b * SEQ) * KVD + kvh * HD };

    {
        const __nv_bfloat16* qs[2] = {
            Qh_g + (size_t)(b * SEQ + qBase) * DIM + h * HD,
            Ql_g + (size_t)(b * SEQ + qBase) * DIM + h * HD };
#pragma unroll
        for (int j = 0; j < 8; j++) {
            int s = tid + (j << 8);
            int arr = s >> 10, r = (s >> 3) & 127, c = s & 7;
            cp16(usm + (uint32_t)((arr * 9216 + r * LDQ + c * 8) * 2),
                 qs[arr] + (size_t)r * DIM + c * 8);
        }
        CP_COMMIT();
    }

    auto issue_kv = [&](int j, int st) {
        int kvBase = j * 128;
        uint32_t base = usm + (uint32_t)((18432 + st * AKV2) * 2);
#pragma unroll
        for (int q = 0; q < 16; q++) {
            int s = tid + (q << 8);
            int arr = s >> 10, r = (s >> 3) & 127, c = s & 7;
            cp16(base + (uint32_t)((arr * 9216 + r * LDQ + c * 8) * 2),
                 kvsrc[arr] + (size_t)(kvBase + r) * KVD + c * 8);
        }
    };

    const int ntiles = qt + 1;
    issue_kv(0, 0);
    CP_COMMIT();

    CP_WAIT1();
    __syncthreads();

    uint32_t qh[4][4], ql[4][4];
    {
        int off0 = (16*w + (lane & 15)) * LDQ + ((lane >> 4) << 3);
#pragma unroll
        for (int kb = 0; kb < 4; kb++) {
            uint32_t off = (uint32_t)((off0 + kb * 16) * 2);
            ldmatrix_x4(qh[kb][0], qh[kb][1], qh[kb][2], qh[kb][3], usm + off);
            ldmatrix_x4(ql[kb][0], ql[kb][1], ql[kb][2], ql[kb][3],
                        usm + (uint32_t)(9216 * 2) + off);
        }
    }

    float o[8][4];
#pragma unroll
    for (int nb = 0; nb < 8; nb++)
#pragma unroll
        for (int q = 0; q < 4; q++) o[nb][q] = 0.f;
    float m0 = -3e38f, m1 = -3e38f, l0 = 0.f, l1 = 0.f;

    const int bN = ((lane >> 4) << 3) + (lane & 7);
    const int bK = ((lane >> 3) & 1) << 3;
    const int vRow = lane & 15, vCol = (lane >> 4) << 3;
    const int r0   = lane >> 2;
    const int c2   = (lane & 3) << 1;
    const int qi0  = wq0 + r0, qi1 = qi0 + 8;

    for (int j = 0; j < ntiles; j++) {
        const int kvBase = j * 128;
        const int st = j & 1;
        if (j + 1 < ntiles) {
            issue_kv(j + 1, st ^ 1);
            CP_COMMIT();
            CP_WAIT1();
        } else {
            CP_WAIT0();
        }
        __syncthreads();

        if (kvBase <= wq0 + 15) {
            const uint32_t kvb = usm + (uint32_t)((18432 + st * AKV2) * 2);
            const uint32_t uKh = kvb, uKl = kvb + 9216 * 2;
            const uint32_t uVh = kvb + 18432 * 2, uVl = kvb + 27648 * 2;

            float sa[16][4];
#pragma unroll
            for (int nb = 0; nb < 16; nb++)
#pragma unroll
                for (int q = 0; q < 4; q++) sa[nb][q] = 0.f;

#pragma unroll
            for (int hf = 0; hf < 2; hf++) {
#pragma unroll
                for (int kb = 0; kb < 4; kb++) {
                    uint32_t bhf[8][2], blf[8][2];
#pragma unroll
                    for (int g = 0; g < 4; g++) {
                        uint32_t off = (uint32_t)((((hf*64 + g*16) + bN) * LDQ
                                                  + kb*16 + bK) * 2);
                        ldmatrix_x4(bhf[2*g][0], bhf[2*g][1],
                                    bhf[2*g+1][0], bhf[2*g+1][1], uKh + off);
                        ldmatrix_x4(blf[2*g][0], blf[2*g][1],
                                    blf[2*g+1][0], blf[2*g+1][1], uKl + off);
                    }
                    float* sp = &sa[hf*8][0];
#pragma unroll
                    for (int nb = 0; nb < 8; nb++) mma_bf16(sp + nb*4, qh[kb], bhf[nb]);
#pragma unroll
                    for (int nb = 0; nb < 8; nb++) mma_bf16(sp + nb*4, qh[kb], blf[nb]);
#pragma unroll
                    for (int nb = 0; nb < 8; nb++) mma_bf16(sp + nb*4, ql[kb], bhf[nb]);
                }
            }

            if (kvBase + 127 > wq0) {
#pragma unroll
                for (int nb = 0; nb < 16; nb++) {
                    int col = kvBase + nb * 8 + c2;
                    if (col     > qi0) sa[nb][0] = -3e38f;
                    if (col + 1 > qi0) sa[nb][1] = -3e38f;
                    if (col     > qi1) sa[nb][2] = -3e38f;
                    if (col + 1 > qi1) sa[nb][3] = -3e38f;
                }
            }

            float mx0 = -3e38f, mx1 = -3e38f;
#pragma unroll
            for (int nb = 0; nb < 16; nb++) {
                mx0 = fmaxf(mx0, fmaxf(sa[nb][0], sa[nb][1]));
                mx1 = fmaxf(mx1, fmaxf(sa[nb][2], sa[nb][3]));
            }
            mx0 = fmaxf(mx0, __shfl_xor_sync(0xffffffffu, mx0, 1));
            mx0 = fmaxf(mx0, __shfl_xor_sync(0xffffffffu, mx0, 2));
            mx1 = fmaxf(mx1, __shfl_xor_sync(0xffffffffu, mx1, 1));
            mx1 = fmaxf(mx1, __shfl_xor_sync(0xffffffffu, mx1, 2));
            float mn0 = fmaxf(m0, mx0), mn1 = fmaxf(m1, mx1);
            float a0 = fexp2c(m0 - mn0), a1 = fexp2c(m1 - mn1);
            m0 = mn0; m1 = mn1;

            float s0 = 0.f, s1 = 0.f;
#pragma unroll
            for (int nb = 0; nb < 16; nb++) {
                sa[nb][0] = fexp2c(sa[nb][0] - mn0); s0 += sa[nb][0];
                sa[nb][1] = fexp2c(sa[nb][1] - mn0); s0 += sa[nb][1];
                sa[nb][2] = fexp2c(sa[nb][2] - mn1); s1 += sa[nb][2];
                sa[nb][3] = fexp2c(sa[nb][3] - mn1); s1 += sa[nb][3];
            }
            s0 += __shfl_xor_sync(0xffffffffu, s0, 1);
            s0 += __shfl_xor_sync(0xffffffffu, s0, 2);
            s1 += __shfl_xor_sync(0xffffffffu, s1, 1);
            s1 += __shfl_xor_sync(0xffffffffu, s1, 2);
            l0 = l0 * a0 + s0;
            l1 = l1 * a1 + s1;
#pragma unroll
            for (int nb = 0; nb < 8; nb++) {
                o[nb][0] *= a0; o[nb][1] *= a0;
                o[nb][2] *= a1; o[nb][3] *= a1;
            }

#pragma unroll
            for (int jk = 0; jk < 8; jk++) {
                uint32_t ph[4], pl[4];
                split2(sa[2*jk][0],   sa[2*jk][1],   ph[0], pl[0]);
                split2(sa[2*jk][2],   sa[2*jk][3],   ph[1], pl[1]);
                split2(sa[2*jk+1][0], sa[2*jk+1][1], ph[2], pl[2]);
                split2(sa[2*jk+1][2], sa[2*jk+1][3], ph[3], pl[3]);
                uint32_t vhf[8][2], vlf[8][2];
#pragma unroll
                for (int g = 0; g < 4; g++) {
                    uint32_t off = (uint32_t)(((jk*16 + vRow) * LDQ + g*16 + vCol) * 2);
                    ldmatrix_x4_trans(vhf[2*g][0], vhf[2*g][1],
                                      vhf[2*g+1][0], vhf[2*g+1][1], uVh + off);
                    ldmatrix_x4_trans(vlf[2*g][0], vlf[2*g][1],
                                      vlf[2*g+1][0], vlf[2*g+1][1], uVl + off);
                }
#pragma unroll
                for (int nb = 0; nb < 8; nb++) mma_bf16(o[nb], ph, vhf[nb]);
#pragma unroll
                for (int nb = 0; nb < 8; nb++) mma_bf16(o[nb], ph, vlf[nb]);
#pragma unroll
                for (int nb = 0; nb < 8; nb++) mma_bf16(o[nb], pl, vhf[nb]);
            }
        }
        __syncthreads();
    }

    float i0 = __fdividef(1.f, l0), i1 = __fdividef(1.f, l1);
#pragma unroll
    for (int nb = 0; nb < 8; nb++) {
        size_t e0 = ((size_t)(b*SEQ + qi0) * DIM + h*HD + nb*8 + c2) >> 1;
        size_t e1 = ((size_t)(b*SEQ + qi1) * DIM + h*HD + nb*8 + c2) >> 1;
        uint32_t h0, lo0, h1, lo1;
        split2(o[nb][0] * i0, o[nb][1] * i0, h0, lo0);
        split2(o[nb][2] * i1, o[nb][3] * i1, h1, lo1);
        ((uint32_t*)Oh)[e0] = h0; ((uint32_t*)Ol)[e0] = lo0;
        ((uint32_t*)Oh)[e1] = h1; ((uint32_t*)Ol)[e1] = lo1;
    }
}

// =============================== Launch ====================================
extern "C" void kernel_launch(void* const* d_in, const int* in_sizes, int n_in,
                              void* d_out, int out_size)
{
    const float* x  = (const float*)d_in[0];
    const float* wq = (const float*)d_in[1];
    const float* wk = (const float*)d_in[2];
    const float* wv = (const float*)d_in[3];
    const float* wo = (const float*)d_in[4];
    float* out = (float*)d_out;

    __nv_bfloat16 *xh, *xl, *wqh, *wql, *wkh, *wkl, *wvh, *wvl, *woh, *wol;
    __nv_bfloat16 *Qh, *Ql, *Kh, *Kl, *Vh, *Vl, *Oh, *Ol;
    cudaGetSymbolAddress((void**)&xh,  g_xh);  cudaGetSymbolAddress((void**)&xl,  g_xl);
    cudaGetSymbolAddress((void**)&wqh, g_wqh); cudaGetSymbolAddress((void**)&wql, g_wql);
    cudaGetSymbolAddress((void**)&wkh, g_wkh); cudaGetSymbolAddress((void**)&wkl, g_wkl);
    cudaGetSymbolAddress((void**)&wvh, g_wvh); cudaGetSymbolAddress((void**)&wvl, g_wvl);
    cudaGetSymbolAddress((void**)&woh, g_woh); cudaGetSymbolAddress((void**)&wol, g_wol);
    cudaGetSymbolAddress((void**)&Qh,  g_Qh);  cudaGetSymbolAddress((void**)&Ql,  g_Ql);
    cudaGetSymbolAddress((void**)&Kh,  g_Kh);  cudaGetSymbolAddress((void**)&Kl,  g_Kl);
    cudaGetSymbolAddress((void**)&Vh,  g_Vh);  cudaGetSymbolAddress((void**)&Vl,  g_Vl);
    cudaGetSymbolAddress((void**)&Oh,  g_Oh);  cudaGetSymbolAddress((void**)&Ol,  g_Ol);

    cudaFuncSetAttribute(gemm_qkv, cudaFuncAttributeMaxDynamicSharedMemorySize, GEMM_SMEM);
    cudaFuncSetAttribute(gemm_o,   cudaFuncAttributeMaxDynamicSharedMemorySize, GEMM_SMEM);
    cudaFuncSetAttribute(attn_ps,  cudaFuncAttributeMaxDynamicSharedMemorySize, ATT_SMEM);

    dim3 blk(256);
    split_all<<<(SPLIT_N4 + 255)/256, blk>>>(x, wq, wk, wv, wo,
        xh, xl, wqh, wql, wkh, wkl, wvh, wvl, woh, wol);

    gemm_qkv<<<dim3(24, MTOT/128), blk, GEMM_SMEM>>>(
        xh, xl, wqh, wql, wkh, wkl, wvh, wvl, Qh, Ql, Kh, Kl, Vh, Vl);
    attn_ps<<<dim3(SEQ/128, NH, BATCH), blk, ATT_SMEM>>>(
        Qh, Ql, Kh, Kl, Vh, Vl, Oh, Ol);
    gemm_o<<<dim3(DIM/128, MTOT/128), blk, GEMM_SMEM>>>(
        Oh, Ol, woh, wol, out);
}